// round 2
// baseline (speedup 1.0000x reference)
#include <cuda_runtime.h>
#include <math.h>

#define BB 2
#define SS 2048
#define HID 1024
#define NH 16
#define DD 64
#define ROT 32
#define MTOT (BB*SS)   // 4096 rows

// Scratch (allocation-free rule: device globals)
__device__ float g_Q[BB*SS*HID];
__device__ float g_K[BB*SS*HID];
__device__ float g_V[BB*SS*HID];
__device__ float g_C[BB*SS*HID];

// ---------------------------------------------------------------------------
// Tiled fp32 GEMM: C[M,N] = A[M,K] @ W[K,N] (+ bias[N]); row-major everywhere.
// 64x64 block tile, K-tile 16, 256 threads, 4x4 micro-tile per thread.
// ---------------------------------------------------------------------------
template<bool HAS_BIAS>
__global__ __launch_bounds__(256)
void gemm64(const float* __restrict__ A, const float* __restrict__ W,
            const float* __restrict__ bias, float* __restrict__ C,
            int M, int N, int K)
{
    __shared__ float As[16][65];   // [kk][row], padded vs 16-way write conflict
    __shared__ float Bs[16][64];   // [kk][col]

    const int tx = threadIdx.x & 15;       // 0..15 -> col group
    const int ty = threadIdx.x >> 4;       // 0..15 -> row group
    const int m0 = blockIdx.y * 64;
    const int n0 = blockIdx.x * 64;

    float acc[4][4];
    #pragma unroll
    for (int i = 0; i < 4; i++)
        #pragma unroll
        for (int j = 0; j < 4; j++) acc[i][j] = 0.f;

    for (int k0 = 0; k0 < K; k0 += 16) {
        // Load A tile 64x16 (store transposed)
        #pragma unroll
        for (int i = threadIdx.x; i < 64 * 16; i += 256) {
            int row = i >> 4, kk = i & 15;
            As[kk][row] = A[(size_t)(m0 + row) * K + k0 + kk];
        }
        // Load W tile 16x64
        #pragma unroll
        for (int i = threadIdx.x; i < 16 * 64; i += 256) {
            int kk = i >> 6, col = i & 63;
            Bs[kk][col] = W[(size_t)(k0 + kk) * N + n0 + col];
        }
        __syncthreads();

        #pragma unroll
        for (int kk = 0; kk < 16; kk++) {
            float a[4];
            #pragma unroll
            for (int i = 0; i < 4; i++) a[i] = As[kk][ty * 4 + i];
            float4 b4 = *reinterpret_cast<const float4*>(&Bs[kk][tx * 4]);
            float b[4] = {b4.x, b4.y, b4.z, b4.w};
            #pragma unroll
            for (int i = 0; i < 4; i++)
                #pragma unroll
                for (int j = 0; j < 4; j++)
                    acc[i][j] = fmaf(a[i], b[j], acc[i][j]);
        }
        __syncthreads();
    }

    // Epilogue
    #pragma unroll
    for (int i = 0; i < 4; i++) {
        int row = m0 + ty * 4 + i;
        int col = n0 + tx * 4;
        float4 r;
        r.x = acc[i][0]; r.y = acc[i][1]; r.z = acc[i][2]; r.w = acc[i][3];
        if (HAS_BIAS) {
            r.x += bias[col + 0]; r.y += bias[col + 1];
            r.z += bias[col + 2]; r.w += bias[col + 3];
        }
        *reinterpret_cast<float4*>(&C[(size_t)row * N + col]) = r;
    }
}

// ---------------------------------------------------------------------------
// Rotary (degenerate: elementwise scale) + fold 1/sqrt(D) into Q.
// sinusoids: (B, 2, S, ROT); sin = [:,0], cos = [:,1].
// even dim d<32:  *(cos - sin);  odd: *(cos + sin)
// ---------------------------------------------------------------------------
__global__ void rotary_scale(float* __restrict__ Q, float* __restrict__ K,
                             const float* __restrict__ sinu)
{
    int idx = blockIdx.x * blockDim.x + threadIdx.x;
    if (idx >= BB * SS * HID) return;
    int d = idx & 63;                 // dim within head
    int s = (idx >> 10) & (SS - 1);   // sequence pos
    int b = idx >> 21;                // batch (idx / (S*HID))
    const float qscale = 0.125f;      // 1/sqrt(64)
    float fq, fk;
    if (d < ROT) {
        float sn = sinu[(((size_t)b * 2 + 0) * SS + s) * ROT + d];
        float cs = sinu[(((size_t)b * 2 + 1) * SS + s) * ROT + d];
        float f = (d & 1) ? (cs + sn) : (cs - sn);
        fq = f * qscale; fk = f;
    } else {
        fq = qscale; fk = 1.f;
    }
    Q[idx] *= fq;
    K[idx] *= fk;
}

// ---------------------------------------------------------------------------
// Flash attention with post-softmax multiplicative bias:
//   O = (sum_k exp(s_k - m) * bias_k * v_k) / (sum_k exp(s_k - m))
// 128 threads/block, 1 q-row per thread, K/V staged 32 rows x 64 dims in smem.
// ---------------------------------------------------------------------------
__global__ __launch_bounds__(128)
void attn_kernel(const float* __restrict__ Q, const float* __restrict__ K,
                 const float* __restrict__ V, const float* __restrict__ bias,
                 float* __restrict__ Ctx)
{
    const int b = blockIdx.z;
    const int h = blockIdx.y;
    const int q = blockIdx.x * 128 + threadIdx.x;

    __shared__ float Ks[32][64];
    __shared__ float Vs[32][64];

    const float* qptr = Q + ((size_t)(b * SS + q)) * HID + h * DD;
    float qr[64];
    #pragma unroll
    for (int d = 0; d < 64; d++) qr[d] = qptr[d];

    float O[64];
    #pragma unroll
    for (int d = 0; d < 64; d++) O[d] = 0.f;
    float m = -1e30f, l = 0.f;

    const float* brow = bias + ((size_t)b * SS + q) * SS;

    for (int k0 = 0; k0 < SS; k0 += 32) {
        for (int i = threadIdx.x; i < 32 * 64; i += 128) {
            int kk = i >> 6, d = i & 63;
            size_t off = ((size_t)(b * SS + k0 + kk)) * HID + h * DD + d;
            Ks[kk][d] = K[off];
            Vs[kk][d] = V[off];
        }
        __syncthreads();

        float sc[32];
        #pragma unroll
        for (int kk = 0; kk < 32; kk++) {
            float s = 0.f;
            #pragma unroll
            for (int d = 0; d < 64; d++) s = fmaf(qr[d], Ks[kk][d], s);
            sc[kk] = s;
        }

        float mt = m;
        #pragma unroll
        for (int kk = 0; kk < 32; kk++) mt = fmaxf(mt, sc[kk]);
        float corr = __expf(m - mt);
        l *= corr;
        #pragma unroll
        for (int d = 0; d < 64; d++) O[d] *= corr;
        m = mt;

        #pragma unroll
        for (int kk = 0; kk < 32; kk++) {
            float p = __expf(sc[kk] - m);
            l += p;
            float w = p * brow[k0 + kk];
            #pragma unroll
            for (int d = 0; d < 64; d++) O[d] = fmaf(w, Vs[kk][d], O[d]);
        }
        __syncthreads();
    }

    float inv = 1.f / l;
    float* optr = Ctx + ((size_t)(b * SS + q)) * HID + h * DD;
    #pragma unroll
    for (int d = 0; d < 64; d++) optr[d] = O[d] * inv;
}

// ---------------------------------------------------------------------------
extern "C" void kernel_launch(void* const* d_in, const int* in_sizes, int n_in,
                              void* d_out, int out_size)
{
    const float* x    = (const float*)d_in[0];
    const float* sinu = (const float*)d_in[1];
    const float* bias = (const float*)d_in[2];
    const float* Wq   = (const float*)d_in[3];
    const float* bq   = (const float*)d_in[4];
    const float* Wk   = (const float*)d_in[5];
    const float* bk   = (const float*)d_in[6];
    const float* Wv   = (const float*)d_in[7];
    const float* bv   = (const float*)d_in[8];
    const float* Wo   = (const float*)d_in[9];
    float* out = (float*)d_out;

    float *Qp, *Kp, *Vp, *Cp;
    cudaGetSymbolAddress((void**)&Qp, g_Q);
    cudaGetSymbolAddress((void**)&Kp, g_K);
    cudaGetSymbolAddress((void**)&Vp, g_V);
    cudaGetSymbolAddress((void**)&Cp, g_C);

    dim3 gg(HID / 64, MTOT / 64);
    dim3 gb(256);

    gemm64<true><<<gg, gb>>>(x, Wq, bq, Qp, MTOT, HID, HID);
    gemm64<true><<<gg, gb>>>(x, Wk, bk, Kp, MTOT, HID, HID);
    gemm64<true><<<gg, gb>>>(x, Wv, bv, Vp, MTOT, HID, HID);

    int nel = BB * SS * HID;
    rotary_scale<<<(nel + 255) / 256, 256>>>(Qp, Kp, sinu);

    attn_kernel<<<dim3(SS / 128, NH, BB), 128>>>(Qp, Kp, Vp, bias, Cp);

    gemm64<false><<<gg, gb>>>(Cp, Wo, nullptr, out, MTOT, HID, HID);
}

// round 5
// speedup vs baseline: 3.4230x; 3.4230x over previous
#include <cuda_runtime.h>
#include <cuda_bf16.h>
#include <math.h>
#include <stdint.h>

#define BB 2
#define SS 2048
#define HIDD 1024
#define NH 16
#define MTOT (BB*SS)          // 4096
#define NELEM (BB*SS*HIDD)    // 4194304

// ---------------- scratch (allocation-free rule: device globals, ~160MB) ------
__device__ float g_Q32[NELEM];
__device__ float g_K32[NELEM];
__device__ float g_V32[NELEM];
__device__ __nv_bfloat16 g_Qh[NELEM], g_Ql[NELEM];
__device__ __nv_bfloat16 g_Kh[NELEM], g_Kl[NELEM];
__device__ float g_Vph[NELEM/2], g_Vpl[NELEM/2];        // key-paired words
__device__ __nv_bfloat16 g_Ch[NELEM], g_Cl[NELEM];
__device__ __nv_bfloat16 g_Xh[NELEM], g_Xl[NELEM];
__device__ float g_Wh[4][(HIDD/2)*HIDD], g_Wl[4][(HIDD/2)*HIDD];  // k-paired words

// ---------------- helpers ----------------
__device__ __forceinline__ uint32_t smem_u32(const void* p){
    return (uint32_t)__cvta_generic_to_shared(p);
}
__device__ __forceinline__ void cp16(uint32_t d, const void* s){
    asm volatile("cp.async.cg.shared.global [%0], [%1], 16;" :: "r"(d), "l"(s));
}
__device__ __forceinline__ void cp_commit(){ asm volatile("cp.async.commit_group;"); }
template<int N> __device__ __forceinline__ void cp_wait(){
    asm volatile("cp.async.wait_group %0;" :: "n"(N));
}
__device__ __forceinline__ void mma16(float* c, const uint32_t* a, const uint32_t* b){
    asm volatile(
        "mma.sync.aligned.m16n8k16.row.col.f32.bf16.bf16.f32 "
        "{%0,%1,%2,%3}, {%4,%5,%6,%7}, {%8,%9}, {%0,%1,%2,%3};"
        : "+f"(c[0]), "+f"(c[1]), "+f"(c[2]), "+f"(c[3])
        : "r"(a[0]), "r"(a[1]), "r"(a[2]), "r"(a[3]), "r"(b[0]), "r"(b[1]));
}
__device__ __forceinline__ void split1(float x, __nv_bfloat16& h, __nv_bfloat16& l){
    h = __float2bfloat16_rn(x);
    l = __float2bfloat16_rn(x - __bfloat162float(h));
}
__device__ __forceinline__ uint32_t pack2(__nv_bfloat16 a, __nv_bfloat16 b){
    __nv_bfloat162 t; t.x = a; t.y = b;
    return *(uint32_t*)&t;
}

// ---------------- prep: split x into bf16 hi/lo (row-major) ----------------
__global__ void split_x_k(const float2* __restrict__ src,
                          __nv_bfloat162* __restrict__ h, __nv_bfloat162* __restrict__ l, int n)
{
    int i = blockIdx.x * blockDim.x + threadIdx.x;
    if (i >= n) return;
    float2 v = src[i];
    __nv_bfloat16 h0, l0, h1, l1;
    split1(v.x, h0, l0); split1(v.y, h1, l1);
    __nv_bfloat162 hh; hh.x = h0; hh.y = h1;
    __nv_bfloat162 ll; ll.x = l0; ll.y = l1;
    h[i] = hh; l[i] = ll;
}

// ---------------- prep: split W into k-paired bf16x2 words ----------------
__global__ void split_w_k(const float* __restrict__ W,
                          uint32_t* __restrict__ Wh, uint32_t* __restrict__ Wl)
{
    int i = blockIdx.x * blockDim.x + threadIdx.x;   // over 512*1024
    if (i >= (HIDD/2)*HIDD) return;
    int n = i & (HIDD-1), kp = i >> 10;
    float x0 = W[(size_t)(2*kp)  *HIDD + n];
    float x1 = W[(size_t)(2*kp+1)*HIDD + n];
    __nv_bfloat16 h0,l0,h1,l1;
    split1(x0,h0,l0); split1(x1,h1,l1);
    Wh[i] = pack2(h0,h1);
    Wl[i] = pack2(l0,l1);
}

// ---------------- rotary (degenerate elementwise) + bf16 split ----------------
__global__ void rotary_split_k(const float* __restrict__ Q32, const float* __restrict__ K32,
                               const float* __restrict__ sinu,
                               __nv_bfloat162* __restrict__ Qh, __nv_bfloat162* __restrict__ Ql,
                               __nv_bfloat162* __restrict__ Kh, __nv_bfloat162* __restrict__ Kl)
{
    int i = blockIdx.x * blockDim.x + threadIdx.x;   // over NELEM/2 words
    if (i >= NELEM/2) return;
    int wj = i & 511;             // word within HID
    int tok = i >> 9;
    int s = tok & (SS-1), b = tok >> 11;
    int d0 = (wj*2) & 63;
    float f0 = 1.f, f1 = 1.f;
    if (d0 < 32){
        const float* sb = sinu + (size_t)b*2*SS*32;
        float sn0 = sb[(size_t)s*32 + d0];
        float cs0 = sb[(size_t)SS*32 + (size_t)s*32 + d0];
        float sn1 = sb[(size_t)s*32 + d0+1];
        float cs1 = sb[(size_t)SS*32 + (size_t)s*32 + d0+1];
        f0 = cs0 - sn0;           // even dims
        f1 = cs1 + sn1;           // odd dims
    }
    float2 q = ((const float2*)Q32)[i];
    float2 k = ((const float2*)K32)[i];
    q.x *= f0 * 0.125f; q.y *= f1 * 0.125f;
    k.x *= f0;          k.y *= f1;
    __nv_bfloat16 h0,l0,h1,l1;
    split1(q.x,h0,l0); split1(q.y,h1,l1);
    { __nv_bfloat162 a,bb2; a.x=h0;a.y=h1; bb2.x=l0;bb2.y=l1; Qh[i]=a; Ql[i]=bb2; }
    split1(k.x,h0,l0); split1(k.y,h1,l1);
    { __nv_bfloat162 a,bb2; a.x=h0;a.y=h1; bb2.x=l0;bb2.y=l1; Kh[i]=a; Kl[i]=bb2; }
}

// ---------------- prep: V key-paired bf16x2 words ----------------
__global__ void prep_v_k(const float* __restrict__ V32,
                         uint32_t* __restrict__ Vph, uint32_t* __restrict__ Vpl)
{
    int i = blockIdx.x * blockDim.x + threadIdx.x;   // over NELEM/2 words
    if (i >= NELEM/2) return;
    int hid = i & (HIDD-1);
    int r = i >> 10;
    int kp = r & (SS/2 - 1), b = r >> 10;
    float v0 = V32[((size_t)(b*SS + 2*kp))  *HIDD + hid];
    float v1 = V32[((size_t)(b*SS + 2*kp+1))*HIDD + hid];
    __nv_bfloat16 h0,l0,h1,l1;
    split1(v0,h0,l0); split1(v1,h1,l1);
    Vph[i] = pack2(h0,h1);
    Vpl[i] = pack2(l0,l1);
}

// ---------------------------------------------------------------------------
// split-bf16 GEMM: C[M,N] = A[M,K] @ W[K,N] (+bias), fp32 out.
// A: bf16 hi/lo row-major. B: k-paired bf16x2 word arrays [K/2][N].
// 128x128 tile, kTile 32, 256 thr (8 warps 2x4), cp.async double-buffered.
// A smem rows padded to 20 words (bank-decorrelating pad, no xor);
// B smem word-swizzle n ^ ((kp&3)<<3).
// ---------------------------------------------------------------------------
__global__ __launch_bounds__(256)
void gemm_sb(const __nv_bfloat16* __restrict__ Ah, const __nv_bfloat16* __restrict__ Al,
             const float* __restrict__ Bh, const float* __restrict__ Bl,
             const float* __restrict__ bias, float* __restrict__ C,
             int M, int N, int K, int has_bias)
{
    extern __shared__ float sm[];
    // A buffers: (st*2+half)*2560 words; B buffers: 10240 + (st*2+half)*2048
    const int tid = threadIdx.x, lane = tid & 31, wid = tid >> 5;
    const int g = lane >> 2, tig = lane & 3;
    const int m0 = blockIdx.y * 128, n0 = blockIdx.x * 128;
    const int wm = (wid >> 2) * 64, wn = (wid & 3) * 32;

    float acc[4][4][4];
    #pragma unroll
    for (int i = 0; i < 4; i++)
        #pragma unroll
        for (int j = 0; j < 4; j++)
            #pragma unroll
            for (int r = 0; r < 4; r++) acc[i][j][r] = 0.f;

    auto loadA = [&](int k0, int st){
        #pragma unroll
        for (int half = 0; half < 2; half++){
            const __nv_bfloat16* S = half ? Al : Ah;
            float* D = sm + (st*2 + half) * 2560;
            #pragma unroll
            for (int i = 0; i < 2; i++){
                int idx = tid + i*256;           // 0..511
                int row = idx >> 2, gw = idx & 3;
                cp16(smem_u32(D + row*20 + gw*4),
                     S + (size_t)(m0+row)*K + k0 + gw*8);
            }
        }
    };
    auto loadB = [&](int k0, int st){
        int kp0 = k0 >> 1;
        #pragma unroll
        for (int half = 0; half < 2; half++){
            const float* S = half ? Bl : Bh;
            float* D = sm + 10240 + (st*2 + half) * 2048;
            #pragma unroll
            for (int i = 0; i < 2; i++){
                int idx = tid + i*256;           // 0..511
                int kp = idx >> 5, gn = idx & 31;
                cp16(smem_u32(D + kp*128 + ((gn ^ ((kp&3)<<1))<<2)),
                     S + (size_t)(kp0+kp)*N + n0 + gn*4);
            }
        }
    };

    loadA(0, 0); loadB(0, 0); cp_commit();
    const int KT = K >> 5;
    for (int kt = 0; kt < KT; kt++){
        int cur = kt & 1;
        if (kt + 1 < KT){
            loadA((kt+1) << 5, cur ^ 1);
            loadB((kt+1) << 5, cur ^ 1);
            cp_commit();
            cp_wait<1>();
        } else cp_wait<0>();
        __syncthreads();

        const float* Ah_s = sm + (cur*2    )*2560;
        const float* Al_s = sm + (cur*2 + 1)*2560;
        const float* Bh_s = sm + 10240 + (cur*2    )*2048;
        const float* Bl_s = sm + 10240 + (cur*2 + 1)*2048;

        #pragma unroll
        for (int ks = 0; ks < 2; ks++){
            uint32_t bh[4][2], bl[4][2];
            #pragma unroll
            for (int nt = 0; nt < 4; nt++){
                int kp = ks*8 + tig;
                int sx = (wn + nt*8 + g) ^ (tig << 3);   // (kp&3)==tig
                bh[nt][0] = *(const uint32_t*)&Bh_s[kp*128 + sx];
                bh[nt][1] = *(const uint32_t*)&Bh_s[(kp+4)*128 + sx];
                bl[nt][0] = *(const uint32_t*)&Bl_s[kp*128 + sx];
                bl[nt][1] = *(const uint32_t*)&Bl_s[(kp+4)*128 + sx];
            }
            #pragma unroll
            for (int mt = 0; mt < 4; mt++){
                int r = wm + mt*16 + g;
                int w0 = ks*8 + tig;
                uint32_t ah[4], al[4];
                ah[0] = *(const uint32_t*)&Ah_s[r*20 + w0];
                ah[1] = *(const uint32_t*)&Ah_s[(r+8)*20 + w0];
                ah[2] = *(const uint32_t*)&Ah_s[r*20 + w0 + 4];
                ah[3] = *(const uint32_t*)&Ah_s[(r+8)*20 + w0 + 4];
                al[0] = *(const uint32_t*)&Al_s[r*20 + w0];
                al[1] = *(const uint32_t*)&Al_s[(r+8)*20 + w0];
                al[2] = *(const uint32_t*)&Al_s[r*20 + w0 + 4];
                al[3] = *(const uint32_t*)&Al_s[(r+8)*20 + w0 + 4];
                #pragma unroll
                for (int nt = 0; nt < 4; nt++){
                    mma16(acc[mt][nt], ah, bh[nt]);
                    mma16(acc[mt][nt], ah, bl[nt]);
                    mma16(acc[mt][nt], al, bh[nt]);
                }
            }
        }
        __syncthreads();
    }

    #pragma unroll
    for (int mt = 0; mt < 4; mt++)
        #pragma unroll
        for (int nt = 0; nt < 4; nt++){
            int row = m0 + wm + mt*16 + g;
            int col = n0 + wn + nt*8 + tig*2;
            float2 v0 = make_float2(acc[mt][nt][0], acc[mt][nt][1]);
            float2 v1 = make_float2(acc[mt][nt][2], acc[mt][nt][3]);
            if (has_bias){
                float bx = bias[col], by = bias[col+1];
                v0.x += bx; v0.y += by; v1.x += bx; v1.y += by;
            }
            *(float2*)&C[(size_t)row*N + col] = v0;
            *(float2*)&C[(size_t)(row+8)*N + col] = v1;
        }
}

// ---------------------------------------------------------------------------
// Fused flash attention, split-bf16 mma, post-softmax multiplicative bias.
// Block: one (b,h) x 128 q rows; 8 warps x 16 q rows; 64-key tiles dbl-buffered.
// grid = (NH, S/128, B) so heads sharing a bias tile run together (L2 reuse).
// ---------------------------------------------------------------------------
__global__ __launch_bounds__(256)
void flash_attn(const __nv_bfloat16* __restrict__ Qh, const __nv_bfloat16* __restrict__ Ql,
                const __nv_bfloat16* __restrict__ Kh, const __nv_bfloat16* __restrict__ Kl,
                const float* __restrict__ Vph, const float* __restrict__ Vpl,
                const float* __restrict__ bias,
                __nv_bfloat16* __restrict__ Ch, __nv_bfloat16* __restrict__ Cl)
{
    extern __shared__ float sm[];
    const int QHo = 0, QLo = 4096;
    const int KH0 = 8192, KL0 = 12288, VH0 = 16384, VL0 = 20480;  // + buf*2048
    const int BI0 = 24576;                                         // + buf*8704
    const int PHo = 41984, PLo = 46080;                            // total 50176 floats

    const int tid = threadIdx.x, lane = tid & 31, wid = tid >> 5;
    const int g = lane >> 2, tig = lane & 3;
    const int h = blockIdx.x, m0 = blockIdx.y * 128, b = blockIdx.z;

    const __nv_bfloat16* Qhg = Qh + ((size_t)(b*SS + m0))*HIDD + h*64;
    const __nv_bfloat16* Qlg = Ql + ((size_t)(b*SS + m0))*HIDD + h*64;

    // Q tile once (both halves)
    #pragma unroll
    for (int i = 0; i < 4; i++){
        int idx = tid + i*256;               // 0..1023
        int row = idx >> 3, gw = idx & 7;
        int dst = row*32 + ((gw ^ (row&7)) << 2);
        cp16(smem_u32(sm + QHo + dst), Qhg + (size_t)row*HIDD + gw*8);
        cp16(smem_u32(sm + QLo + dst), Qlg + (size_t)row*HIDD + gw*8);
    }

    auto load_tile = [&](int kt, int st){
        const __nv_bfloat16* khg = Kh + ((size_t)(b*SS + kt*64))*HIDD + h*64;
        const __nv_bfloat16* klg = Kl + ((size_t)(b*SS + kt*64))*HIDD + h*64;
        #pragma unroll
        for (int i = 0; i < 2; i++){
            int idx = tid + i*256;           // 0..511
            int row = idx >> 3, gw = idx & 7;
            int dst = row*32 + ((gw ^ (row&7)) << 2);
            cp16(smem_u32(sm + KH0 + st*2048 + dst), khg + (size_t)row*HIDD + gw*8);
            cp16(smem_u32(sm + KL0 + st*2048 + dst), klg + (size_t)row*HIDD + gw*8);
        }
        const float* vhg = Vph + ((size_t)(b*(SS/2) + kt*32))*HIDD + h*64;
        const float* vlg = Vpl + ((size_t)(b*(SS/2) + kt*32))*HIDD + h*64;
        #pragma unroll
        for (int i = 0; i < 2; i++){
            int idx = tid + i*256;           // 0..511
            int kp = idx >> 4, gw = idx & 15;
            int dst = kp*64 + ((gw ^ ((kp&3)<<1)) << 2);
            cp16(smem_u32(sm + VH0 + st*2048 + dst), vhg + (size_t)kp*HIDD + gw*4);
            cp16(smem_u32(sm + VL0 + st*2048 + dst), vlg + (size_t)kp*HIDD + gw*4);
        }
        const float* bg = bias + ((size_t)(b*SS + m0))*SS + kt*64;
        #pragma unroll
        for (int i = 0; i < 8; i++){
            int idx = tid + i*256;           // 0..2047
            int row = idx >> 4, gw = idx & 15;
            cp16(smem_u32(sm + BI0 + st*8704 + row*68 + gw*4),
                 bg + (size_t)row*SS + gw*4);
        }
    };

    load_tile(0, 0); cp_commit();

    float acc_o[8][4];
    #pragma unroll
    for (int nt = 0; nt < 8; nt++)
        #pragma unroll
        for (int r = 0; r < 4; r++) acc_o[nt][r] = 0.f;
    float mrow0 = -1e30f, mrow1 = -1e30f;
    float lrow0 = 0.f, lrow1 = 0.f;

    const int r   = wid*16 + g;
    const int swr = (r & 7) << 2;            // == g<<2
    const int rA0 = r*32, rA1 = (r+8)*32;

    for (int kt = 0; kt < SS/64; kt++){
        int cur = kt & 1;
        if (kt + 1 < SS/64){ load_tile(kt+1, cur^1); cp_commit(); cp_wait<1>(); }
        else cp_wait<0>();
        __syncthreads();

        const float* Kph = sm + KH0 + cur*2048;
        const float* Kpl = sm + KL0 + cur*2048;
        const float* Vsh = sm + VH0 + cur*2048;
        const float* Vsl = sm + VL0 + cur*2048;
        const float* Bp  = sm + BI0 + cur*8704;

        // ---- S = Q . K^T ----
        float acc_s[8][4];
        #pragma unroll
        for (int nt = 0; nt < 8; nt++)
            #pragma unroll
            for (int q = 0; q < 4; q++) acc_s[nt][q] = 0.f;

        #pragma unroll
        for (int ks = 0; ks < 4; ks++){
            int w0 = ks*8 + tig;
            uint32_t qhf[4], qlf[4];
            qhf[0] = *(const uint32_t*)&sm[QHo + rA0 + (w0 ^ swr)];
            qhf[1] = *(const uint32_t*)&sm[QHo + rA1 + (w0 ^ swr)];
            qhf[2] = *(const uint32_t*)&sm[QHo + rA0 + ((w0+4) ^ swr)];
            qhf[3] = *(const uint32_t*)&sm[QHo + rA1 + ((w0+4) ^ swr)];
            qlf[0] = *(const uint32_t*)&sm[QLo + rA0 + (w0 ^ swr)];
            qlf[1] = *(const uint32_t*)&sm[QLo + rA1 + (w0 ^ swr)];
            qlf[2] = *(const uint32_t*)&sm[QLo + rA0 + ((w0+4) ^ swr)];
            qlf[3] = *(const uint32_t*)&sm[QLo + rA1 + ((w0+4) ^ swr)];
            #pragma unroll
            for (int nt = 0; nt < 8; nt++){
                int n = nt*8 + g;
                int ro = n*32, swn = (n&7) << 2;
                uint32_t khf[2], klf[2];
                khf[0] = *(const uint32_t*)&Kph[ro + (w0 ^ swn)];
                khf[1] = *(const uint32_t*)&Kph[ro + ((w0+4) ^ swn)];
                klf[0] = *(const uint32_t*)&Kpl[ro + (w0 ^ swn)];
                klf[1] = *(const uint32_t*)&Kpl[ro + ((w0+4) ^ swn)];
                mma16(acc_s[nt], qhf, khf);
                mma16(acc_s[nt], qhf, klf);
                mma16(acc_s[nt], qlf, khf);
            }
        }

        // ---- streaming softmax update ----
        float mx0 = acc_s[0][0], mx1 = acc_s[0][2];
        #pragma unroll
        for (int nt = 0; nt < 8; nt++){
            mx0 = fmaxf(mx0, fmaxf(acc_s[nt][0], acc_s[nt][1]));
            mx1 = fmaxf(mx1, fmaxf(acc_s[nt][2], acc_s[nt][3]));
        }
        #pragma unroll
        for (int o = 1; o < 4; o <<= 1){
            mx0 = fmaxf(mx0, __shfl_xor_sync(0xffffffffu, mx0, o));
            mx1 = fmaxf(mx1, __shfl_xor_sync(0xffffffffu, mx1, o));
        }
        float mn0 = fmaxf(mrow0, mx0);
        float mn1 = fmaxf(mrow1, mx1);
        float cr0 = __expf(mrow0 - mn0);
        float cr1 = __expf(mrow1 - mn1);
        mrow0 = mn0; mrow1 = mn1;
        lrow0 *= cr0; lrow1 *= cr1;
        #pragma unroll
        for (int nt = 0; nt < 8; nt++){
            acc_o[nt][0] *= cr0; acc_o[nt][1] *= cr0;
            acc_o[nt][2] *= cr1; acc_o[nt][3] *= cr1;
        }

        // exp, accumulate l (bias excluded), stage split P*bias into smem
        #pragma unroll
        for (int nt = 0; nt < 8; nt++){
            float p0 = __expf(acc_s[nt][0] - mn0);
            float p1 = __expf(acc_s[nt][1] - mn0);
            float p2 = __expf(acc_s[nt][2] - mn1);
            float p3 = __expf(acc_s[nt][3] - mn1);
            lrow0 += p0 + p1;
            lrow1 += p2 + p3;
            int col = nt*8 + tig*2;
            float2 b0 = *(const float2*)&Bp[r*68 + col];
            float2 b1 = *(const float2*)&Bp[(r+8)*68 + col];
            float v0 = p0*b0.x, v1 = p1*b0.y, v2 = p2*b1.x, v3 = p3*b1.y;
            __nv_bfloat16 h0,l0,h1,l1,h2,l2,h3,l3;
            split1(v0,h0,l0); split1(v1,h1,l1);
            split1(v2,h2,l2); split1(v3,h3,l3);
            int wc = (nt*4 + tig) ^ swr;
            *(uint32_t*)&sm[PHo + rA0 + wc] = pack2(h0,h1);
            *(uint32_t*)&sm[PHo + rA1 + wc] = pack2(h2,h3);
            *(uint32_t*)&sm[PLo + rA0 + wc] = pack2(l0,l1);
            *(uint32_t*)&sm[PLo + rA1 + wc] = pack2(l2,l3);
        }
        __syncwarp();

        // ---- O += P . V ----
        #pragma unroll
        for (int ks = 0; ks < 4; ks++){
            int w0 = ks*8 + tig;
            uint32_t phf[4], plf[4];
            phf[0] = *(const uint32_t*)&sm[PHo + rA0 + (w0 ^ swr)];
            phf[1] = *(const uint32_t*)&sm[PHo + rA1 + (w0 ^ swr)];
            phf[2] = *(const uint32_t*)&sm[PHo + rA0 + ((w0+4) ^ swr)];
            phf[3] = *(const uint32_t*)&sm[PHo + rA1 + ((w0+4) ^ swr)];
            plf[0] = *(const uint32_t*)&sm[PLo + rA0 + (w0 ^ swr)];
            plf[1] = *(const uint32_t*)&sm[PLo + rA1 + (w0 ^ swr)];
            plf[2] = *(const uint32_t*)&sm[PLo + rA0 + ((w0+4) ^ swr)];
            plf[3] = *(const uint32_t*)&sm[PLo + rA1 + ((w0+4) ^ swr)];
            int base0 = w0*64, base1 = (w0+4)*64;
            int swv = tig << 3;                    // (kp&3)==tig
            #pragma unroll
            for (int nt = 0; nt < 8; nt++){
                int d = nt*8 + g;
                uint32_t vhf[2], vlf[2];
                vhf[0] = *(const uint32_t*)&Vsh[base0 + (d ^ swv)];
                vhf[1] = *(const uint32_t*)&Vsh[base1 + (d ^ swv)];
                vlf[0] = *(const uint32_t*)&Vsl[base0 + (d ^ swv)];
                vlf[1] = *(const uint32_t*)&Vsl[base1 + (d ^ swv)];
                mma16(acc_o[nt], phf, vhf);
                mma16(acc_o[nt], phf, vlf);
                mma16(acc_o[nt], plf, vhf);
            }
        }
        __syncthreads();
    }

    // quad-reduce l, normalize, write split context
    #pragma unroll
    for (int o = 1; o < 4; o <<= 1){
        lrow0 += __shfl_xor_sync(0xffffffffu, lrow0, o);
        lrow1 += __shfl_xor_sync(0xffffffffu, lrow1, o);
    }
    float inv0 = 1.f / lrow0, inv1 = 1.f / lrow1;
    int grow = m0 + r;
    #pragma unroll
    for (int nt = 0; nt < 8; nt++){
        int col = h*64 + nt*8 + tig*2;
        float o0 = acc_o[nt][0]*inv0, o1 = acc_o[nt][1]*inv0;
        float o2 = acc_o[nt][2]*inv1, o3 = acc_o[nt][3]*inv1;
        __nv_bfloat16 h0,l0,h1,l1,h2,l2,h3,l3;
        split1(o0,h0,l0); split1(o1,h1,l1);
        split1(o2,h2,l2); split1(o3,h3,l3);
        size_t off0 = ((size_t)(b*SS + grow    ))*HIDD + col;
        size_t off1 = ((size_t)(b*SS + grow + 8))*HIDD + col;
        *(uint32_t*)&Ch[off0] = pack2(h0,h1);
        *(uint32_t*)&Cl[off0] = pack2(l0,l1);
        *(uint32_t*)&Ch[off1] = pack2(h2,h3);
        *(uint32_t*)&Cl[off1] = pack2(l2,l3);
    }
}

// ---------------------------------------------------------------------------
extern "C" void kernel_launch(void* const* d_in, const int* in_sizes, int n_in,
                              void* d_out, int out_size)
{
    const float* x    = (const float*)d_in[0];
    const float* sinu = (const float*)d_in[1];
    const float* bias = (const float*)d_in[2];
    const float* Wq   = (const float*)d_in[3];
    const float* bq   = (const float*)d_in[4];
    const float* Wk   = (const float*)d_in[5];
    const float* bk   = (const float*)d_in[6];
    const float* Wv   = (const float*)d_in[7];
    const float* bv   = (const float*)d_in[8];
    const float* Wo   = (const float*)d_in[9];
    float* out = (float*)d_out;

    float *Q32, *K32, *V32, *Vph, *Vpl, *Wh, *Wl;
    __nv_bfloat16 *Qh, *Ql, *Kh, *Kl, *Ch, *Cl, *Xh, *Xl;
    cudaGetSymbolAddress((void**)&Q32, g_Q32);
    cudaGetSymbolAddress((void**)&K32, g_K32);
    cudaGetSymbolAddress((void**)&V32, g_V32);
    cudaGetSymbolAddress((void**)&Qh, g_Qh);  cudaGetSymbolAddress((void**)&Ql, g_Ql);
    cudaGetSymbolAddress((void**)&Kh, g_Kh);  cudaGetSymbolAddress((void**)&Kl, g_Kl);
    cudaGetSymbolAddress((void**)&Vph, g_Vph); cudaGetSymbolAddress((void**)&Vpl, g_Vpl);
    cudaGetSymbolAddress((void**)&Ch, g_Ch);  cudaGetSymbolAddress((void**)&Cl, g_Cl);
    cudaGetSymbolAddress((void**)&Xh, g_Xh);  cudaGetSymbolAddress((void**)&Xl, g_Xl);
    cudaGetSymbolAddress((void**)&Wh, g_Wh);
    cudaGetSymbolAddress((void**)&Wl, g_Wl);
    const int WSTRIDE = (HIDD/2)*HIDD;

    cudaFuncSetAttribute(gemm_sb,    cudaFuncAttributeMaxDynamicSharedMemorySize, 73728);
    cudaFuncSetAttribute(flash_attn, cudaFuncAttributeMaxDynamicSharedMemorySize, 200704);

    // prep: splits
    int nwx = NELEM / 2;
    split_x_k<<<(nwx + 255)/256, 256>>>((const float2*)x,
        (__nv_bfloat162*)Xh, (__nv_bfloat162*)Xl, nwx);
    int nww = WSTRIDE;
    split_w_k<<<(nww + 255)/256, 256>>>(Wq, (uint32_t*)(Wh + 0*WSTRIDE), (uint32_t*)(Wl + 0*WSTRIDE));
    split_w_k<<<(nww + 255)/256, 256>>>(Wk, (uint32_t*)(Wh + 1*WSTRIDE), (uint32_t*)(Wl + 1*WSTRIDE));
    split_w_k<<<(nww + 255)/256, 256>>>(Wv, (uint32_t*)(Wh + 2*WSTRIDE), (uint32_t*)(Wl + 2*WSTRIDE));
    split_w_k<<<(nww + 255)/256, 256>>>(Wo, (uint32_t*)(Wh + 3*WSTRIDE), (uint32_t*)(Wl + 3*WSTRIDE));

    // projections
    dim3 gg(HIDD/128, MTOT/128);   // (8, 32)
    gemm_sb<<<gg, 256, 73728>>>(Xh, Xl, Wh + 0*WSTRIDE, Wl + 0*WSTRIDE, bq, Q32, MTOT, HIDD, HIDD, 1);
    gemm_sb<<<gg, 256, 73728>>>(Xh, Xl, Wh + 1*WSTRIDE, Wl + 1*WSTRIDE, bk, K32, MTOT, HIDD, HIDD, 1);
    gemm_sb<<<gg, 256, 73728>>>(Xh, Xl, Wh + 2*WSTRIDE, Wl + 2*WSTRIDE, bv, V32, MTOT, HIDD, HIDD, 1);

    // rotary + splits, V pairing
    rotary_split_k<<<(NELEM/2 + 255)/256, 256>>>(Q32, K32, sinu,
        (__nv_bfloat162*)Qh, (__nv_bfloat162*)Ql, (__nv_bfloat162*)Kh, (__nv_bfloat162*)Kl);
    prep_v_k<<<(NELEM/2 + 255)/256, 256>>>(V32, (uint32_t*)Vph, (uint32_t*)Vpl);

    // fused attention (h fastest for bias L2 reuse)
    flash_attn<<<dim3(NH, SS/128, BB), 256, 200704>>>(Qh, Ql, Kh, Kl, Vph, Vpl, bias, Ch, Cl);

    // output projection
    gemm_sb<<<gg, 256, 73728>>>(Ch, Cl, Wh + 3*WSTRIDE, Wl + 3*WSTRIDE, nullptr, out, MTOT, HIDD, HIDD, 0);
}

// round 8
// speedup vs baseline: 3.9353x; 1.1496x over previous
#include <cuda_runtime.h>
#include <cuda_bf16.h>
#include <cuda_fp16.h>
#include <math.h>
#include <stdint.h>

#define BB 2
#define SS 2048
#define HIDD 1024
#define NH 16
#define MTOT (BB*SS)          // 4096
#define NELEM (BB*SS*HIDD)    // 4194304

// ---------------- scratch (allocation-free rule: device globals, ~150MB) ------
__device__ float g_Q32[NELEM];
__device__ float g_K32[NELEM];
__device__ float g_V32[NELEM];
__device__ __half g_Qh[NELEM], g_Ql[NELEM];
__device__ __half g_Kh[NELEM], g_Kl[NELEM];
__device__ float g_Vp[NELEM/2];                          // token-paired fp16x2 words
__device__ __nv_bfloat16 g_Ch[NELEM], g_Cl[NELEM];
__device__ __nv_bfloat16 g_Xh[NELEM], g_Xl[NELEM];
__device__ float g_Wh[4][(HIDD/2)*HIDD], g_Wl[4][(HIDD/2)*HIDD];  // k-paired words

// ---------------- helpers ----------------
__device__ __forceinline__ uint32_t smem_u32(const void* p){
    return (uint32_t)__cvta_generic_to_shared(p);
}
__device__ __forceinline__ void cp16(uint32_t d, const void* s){
    asm volatile("cp.async.cg.shared.global [%0], [%1], 16;" :: "r"(d), "l"(s));
}
__device__ __forceinline__ void cp_commit(){ asm volatile("cp.async.commit_group;"); }
template<int N> __device__ __forceinline__ void cp_wait(){
    asm volatile("cp.async.wait_group %0;" :: "n"(N));
}
// bf16 mma (projection GEMMs)
__device__ __forceinline__ void mma16(float* c, const uint32_t* a, const uint32_t* b){
    asm volatile(
        "mma.sync.aligned.m16n8k16.row.col.f32.bf16.bf16.f32 "
        "{%0,%1,%2,%3}, {%4,%5,%6,%7}, {%8,%9}, {%0,%1,%2,%3};"
        : "+f"(c[0]), "+f"(c[1]), "+f"(c[2]), "+f"(c[3])
        : "r"(a[0]), "r"(a[1]), "r"(a[2]), "r"(a[3]), "r"(b[0]), "r"(b[1]));
}
// fp16 mma (attention)
__device__ __forceinline__ void mma16h(float* c, const uint32_t* a, const uint32_t* b){
    asm volatile(
        "mma.sync.aligned.m16n8k16.row.col.f32.f16.f16.f32 "
        "{%0,%1,%2,%3}, {%4,%5,%6,%7}, {%8,%9}, {%0,%1,%2,%3};"
        : "+f"(c[0]), "+f"(c[1]), "+f"(c[2]), "+f"(c[3])
        : "r"(a[0]), "r"(a[1]), "r"(a[2]), "r"(a[3]), "r"(b[0]), "r"(b[1]));
}
__device__ __forceinline__ void split1(float x, __nv_bfloat16& h, __nv_bfloat16& l){
    h = __float2bfloat16_rn(x);
    l = __float2bfloat16_rn(x - __bfloat162float(h));
}
__device__ __forceinline__ void split1h(float x, __half& h, __half& l){
    h = __float2half_rn(x);
    l = __float2half_rn(x - __half2float(h));
}
__device__ __forceinline__ uint32_t pack2(__nv_bfloat16 a, __nv_bfloat16 b){
    __nv_bfloat162 t; t.x = a; t.y = b;
    return *(uint32_t*)&t;
}
__device__ __forceinline__ uint32_t pack2h(__half a, __half b){
    __half2 t; t.x = a; t.y = b;
    return *(uint32_t*)&t;
}

// ---------------- prep: split x into bf16 hi/lo (row-major) ----------------
__global__ void split_x_k(const float2* __restrict__ src,
                          __nv_bfloat162* __restrict__ h, __nv_bfloat162* __restrict__ l, int n)
{
    int i = blockIdx.x * blockDim.x + threadIdx.x;
    if (i >= n) return;
    float2 v = src[i];
    __nv_bfloat16 h0, l0, h1, l1;
    split1(v.x, h0, l0); split1(v.y, h1, l1);
    __nv_bfloat162 hh; hh.x = h0; hh.y = h1;
    __nv_bfloat162 ll; ll.x = l0; ll.y = l1;
    h[i] = hh; l[i] = ll;
}

// ---------------- prep: split W into k-paired bf16x2 words ----------------
__global__ void split_w_k(const float* __restrict__ W,
                          uint32_t* __restrict__ Wh, uint32_t* __restrict__ Wl)
{
    int i = blockIdx.x * blockDim.x + threadIdx.x;   // over 512*1024
    if (i >= (HIDD/2)*HIDD) return;
    int n = i & (HIDD-1), kp = i >> 10;
    float x0 = W[(size_t)(2*kp)  *HIDD + n];
    float x1 = W[(size_t)(2*kp+1)*HIDD + n];
    __nv_bfloat16 h0,l0,h1,l1;
    split1(x0,h0,l0); split1(x1,h1,l1);
    Wh[i] = pack2(h0,h1);
    Wl[i] = pack2(l0,l1);
}

// ---------------- rotary (degenerate elementwise) + fp16 split ----------------
__global__ void rotary_split_k(const float* __restrict__ Q32, const float* __restrict__ K32,
                               const float* __restrict__ sinu,
                               __half2* __restrict__ Qh, __half2* __restrict__ Ql,
                               __half2* __restrict__ Kh, __half2* __restrict__ Kl)
{
    int i = blockIdx.x * blockDim.x + threadIdx.x;   // over NELEM/2 words
    if (i >= NELEM/2) return;
    int wj = i & 511;             // word within HID
    int tok = i >> 9;
    int s = tok & (SS-1), b = tok >> 11;
    int d0 = (wj*2) & 63;
    float f0 = 1.f, f1 = 1.f;
    if (d0 < 32){
        const float* sb = sinu + (size_t)b*2*SS*32;
        float sn0 = sb[(size_t)s*32 + d0];
        float cs0 = sb[(size_t)SS*32 + (size_t)s*32 + d0];
        float sn1 = sb[(size_t)s*32 + d0+1];
        float cs1 = sb[(size_t)SS*32 + (size_t)s*32 + d0+1];
        f0 = cs0 - sn0;           // even dims
        f1 = cs1 + sn1;           // odd dims
    }
    float2 q = ((const float2*)Q32)[i];
    float2 k = ((const float2*)K32)[i];
    q.x *= f0 * 0.125f; q.y *= f1 * 0.125f;
    k.x *= f0;          k.y *= f1;
    __half h0,l0,h1,l1;
    split1h(q.x,h0,l0); split1h(q.y,h1,l1);
    { __half2 a,bb2; a.x=h0;a.y=h1; bb2.x=l0;bb2.y=l1; Qh[i]=a; Ql[i]=bb2; }
    split1h(k.x,h0,l0); split1h(k.y,h1,l1);
    { __half2 a,bb2; a.x=h0;a.y=h1; bb2.x=l0;bb2.y=l1; Kh[i]=a; Kl[i]=bb2; }
}

// ---------------- prep: V key-paired fp16x2 words (single precision level) ----
__global__ void prep_v_k(const float* __restrict__ V32, uint32_t* __restrict__ Vp)
{
    int i = blockIdx.x * blockDim.x + threadIdx.x;   // over NELEM/2 words
    if (i >= NELEM/2) return;
    int hid = i & (HIDD-1);
    int r = i >> 10;
    int kp = r & (SS/2 - 1), b = r >> 10;
    float v0 = V32[((size_t)(b*SS + 2*kp))  *HIDD + hid];
    float v1 = V32[((size_t)(b*SS + 2*kp+1))*HIDD + hid];
    Vp[i] = pack2h(__float2half_rn(v0), __float2half_rn(v1));
}

// ---------------------------------------------------------------------------
// split-bf16 GEMM (projections/output): C[M,N] = A[M,K] @ W[K,N] (+bias).
// Verbatim from R5 (passing).
// ---------------------------------------------------------------------------
__global__ __launch_bounds__(256)
void gemm_sb(const __nv_bfloat16* __restrict__ Ah, const __nv_bfloat16* __restrict__ Al,
             const float* __restrict__ Bh, const float* __restrict__ Bl,
             const float* __restrict__ bias, float* __restrict__ C,
             int M, int N, int K, int has_bias)
{
    extern __shared__ float smg[];
    const int tid = threadIdx.x, lane = tid & 31, wid = tid >> 5;
    const int g = lane >> 2, tig = lane & 3;
    const int m0 = blockIdx.y * 128, n0 = blockIdx.x * 128;
    const int wm = (wid >> 2) * 64, wn = (wid & 3) * 32;

    float acc[4][4][4];
    #pragma unroll
    for (int i = 0; i < 4; i++)
        #pragma unroll
        for (int j = 0; j < 4; j++)
            #pragma unroll
            for (int r = 0; r < 4; r++) acc[i][j][r] = 0.f;

    auto loadA = [&](int k0, int st){
        #pragma unroll
        for (int half = 0; half < 2; half++){
            const __nv_bfloat16* S = half ? Al : Ah;
            float* D = smg + (st*2 + half) * 2560;
            #pragma unroll
            for (int i = 0; i < 2; i++){
                int idx = tid + i*256;
                int row = idx >> 2, gw = idx & 3;
                cp16(smem_u32(D + row*20 + gw*4),
                     S + (size_t)(m0+row)*K + k0 + gw*8);
            }
        }
    };
    auto loadB = [&](int k0, int st){
        int kp0 = k0 >> 1;
        #pragma unroll
        for (int half = 0; half < 2; half++){
            const float* S = half ? Bl : Bh;
            float* D = smg + 10240 + (st*2 + half) * 2048;
            #pragma unroll
            for (int i = 0; i < 2; i++){
                int idx = tid + i*256;
                int kp = idx >> 5, gn = idx & 31;
                cp16(smem_u32(D + kp*128 + ((gn ^ ((kp&3)<<1))<<2)),
                     S + (size_t)(kp0+kp)*N + n0 + gn*4);
            }
        }
    };

    loadA(0, 0); loadB(0, 0); cp_commit();
    const int KT = K >> 5;
    for (int kt = 0; kt < KT; kt++){
        int cur = kt & 1;
        if (kt + 1 < KT){
            loadA((kt+1) << 5, cur ^ 1);
            loadB((kt+1) << 5, cur ^ 1);
            cp_commit();
            cp_wait<1>();
        } else cp_wait<0>();
        __syncthreads();

        const float* Ah_s = smg + (cur*2    )*2560;
        const float* Al_s = smg + (cur*2 + 1)*2560;
        const float* Bh_s = smg + 10240 + (cur*2    )*2048;
        const float* Bl_s = smg + 10240 + (cur*2 + 1)*2048;

        #pragma unroll
        for (int ks = 0; ks < 2; ks++){
            uint32_t bh[4][2], bl[4][2];
            #pragma unroll
            for (int nt = 0; nt < 4; nt++){
                int kp = ks*8 + tig;
                int sx = (wn + nt*8 + g) ^ (tig << 3);
                bh[nt][0] = *(const uint32_t*)&Bh_s[kp*128 + sx];
                bh[nt][1] = *(const uint32_t*)&Bh_s[(kp+4)*128 + sx];
                bl[nt][0] = *(const uint32_t*)&Bl_s[kp*128 + sx];
                bl[nt][1] = *(const uint32_t*)&Bl_s[(kp+4)*128 + sx];
            }
            #pragma unroll
            for (int mt = 0; mt < 4; mt++){
                int r = wm + mt*16 + g;
                int w0 = ks*8 + tig;
                uint32_t ah[4], al[4];
                ah[0] = *(const uint32_t*)&Ah_s[r*20 + w0];
                ah[1] = *(const uint32_t*)&Ah_s[(r+8)*20 + w0];
                ah[2] = *(const uint32_t*)&Ah_s[r*20 + w0 + 4];
                ah[3] = *(const uint32_t*)&Ah_s[(r+8)*20 + w0 + 4];
                al[0] = *(const uint32_t*)&Al_s[r*20 + w0];
                al[1] = *(const uint32_t*)&Al_s[(r+8)*20 + w0];
                al[2] = *(const uint32_t*)&Al_s[r*20 + w0 + 4];
                al[3] = *(const uint32_t*)&Al_s[(r+8)*20 + w0 + 4];
                #pragma unroll
                for (int nt = 0; nt < 4; nt++){
                    mma16(acc[mt][nt], ah, bh[nt]);
                    mma16(acc[mt][nt], ah, bl[nt]);
                    mma16(acc[mt][nt], al, bh[nt]);
                }
            }
        }
        __syncthreads();
    }

    #pragma unroll
    for (int mt = 0; mt < 4; mt++)
        #pragma unroll
        for (int nt = 0; nt < 4; nt++){
            int row = m0 + wm + mt*16 + g;
            int col = n0 + wn + nt*8 + tig*2;
            float2 v0 = make_float2(acc[mt][nt][0], acc[mt][nt][1]);
            float2 v1 = make_float2(acc[mt][nt][2], acc[mt][nt][3]);
            if (has_bias){
                float bx = bias[col], by = bias[col+1];
                v0.x += bx; v0.y += by; v1.x += bx; v1.y += by;
            }
            *(float2*)&C[(size_t)row*N + col] = v0;
            *(float2*)&C[(size_t)(row+8)*N + col] = v1;
        }
}

// ---------------------------------------------------------------------------
// Fused flash attention, fp16 mma, post-softmax multiplicative bias.
// QK: chunks 0-1 (rotary dims) 3-mma split; chunks 2-3 single fp16 (err 2.8e-4).
// PV: P 2-level fp16 (exact) x V single fp16 (err 2.8e-4). Running max kept.
// ---------------------------------------------------------------------------
__global__ __launch_bounds__(256)
void flash_attn(const __half* __restrict__ Qh, const __half* __restrict__ Ql,
                const __half* __restrict__ Kh, const __half* __restrict__ Kl,
                const float* __restrict__ Vp, const float* __restrict__ bias,
                __nv_bfloat16* __restrict__ Ch, __nv_bfloat16* __restrict__ Cl)
{
    extern __shared__ float sm[];
    const int QHo = 0, QLo = 4096;
    const int KH0 = 8192, KL0 = 12288;    // + st*2048
    const int V0  = 16384;                 // + st*2048
    const int BI0 = 20480;                 // + st*8704
    const int PHo = 37888, PLo = 41984;    // total 46080 floats

    const int tid = threadIdx.x, lane = tid & 31, wid = tid >> 5;
    const int g = lane >> 2, tig = lane & 3;
    const int h = blockIdx.x, m0 = blockIdx.y * 128, b = blockIdx.z;

    const __half* Qhg = Qh + ((size_t)(b*SS + m0))*HIDD + h*64;
    const __half* Qlg = Ql + ((size_t)(b*SS + m0))*HIDD + h*64;

    #pragma unroll
    for (int i = 0; i < 4; i++){
        int idx = tid + i*256;
        int row = idx >> 3, gw = idx & 7;
        int dst = row*32 + ((gw ^ (row&7)) << 2);
        cp16(smem_u32(sm + QHo + dst), Qhg + (size_t)row*HIDD + gw*8);
        cp16(smem_u32(sm + QLo + dst), Qlg + (size_t)row*HIDD + gw*8);
    }

    auto load_tile = [&](int kt, int st){
        const __half* khg = Kh + ((size_t)(b*SS + kt*64))*HIDD + h*64;
        const __half* klg = Kl + ((size_t)(b*SS + kt*64))*HIDD + h*64;
        #pragma unroll
        for (int i = 0; i < 2; i++){
            int idx = tid + i*256;
            int row = idx >> 3, gw = idx & 7;
            int dst = row*32 + ((gw ^ (row&7)) << 2);
            cp16(smem_u32(sm + KH0 + st*2048 + dst), khg + (size_t)row*HIDD + gw*8);
            cp16(smem_u32(sm + KL0 + st*2048 + dst), klg + (size_t)row*HIDD + gw*8);
        }
        const float* vg = Vp + ((size_t)(b*(SS/2) + kt*32))*HIDD + h*64;
        #pragma unroll
        for (int i = 0; i < 2; i++){
            int idx = tid + i*256;
            int kp = idx >> 4, gw = idx & 15;
            int dst = kp*64 + ((gw ^ ((kp&3)<<1)) << 2);
            cp16(smem_u32(sm + V0 + st*2048 + dst), vg + (size_t)kp*HIDD + gw*4);
        }
        const float* bg = bias + ((size_t)(b*SS + m0))*SS + kt*64;
        #pragma unroll
        for (int i = 0; i < 8; i++){
            int idx = tid + i*256;
            int row = idx >> 4, gw = idx & 15;
            cp16(smem_u32(sm + BI0 + st*8704 + row*68 + gw*4),
                 bg + (size_t)row*SS + gw*4);
        }
    };

    load_tile(0, 0); cp_commit();

    float acc_o[8][4];
    #pragma unroll
    for (int nt = 0; nt < 8; nt++)
        #pragma unroll
        for (int r = 0; r < 4; r++) acc_o[nt][r] = 0.f;
    float mrow0 = -1e30f, mrow1 = -1e30f;
    float lrow0 = 0.f, lrow1 = 0.f;

    const int r   = wid*16 + g;
    const int swr = (r & 7) << 2;
    const int rA0 = r*32, rA1 = (r+8)*32;

    for (int kt = 0; kt < SS/64; kt++){
        int cur = kt & 1;
        if (kt + 1 < SS/64){ load_tile(kt+1, cur^1); cp_commit(); cp_wait<1>(); }
        else cp_wait<0>();
        __syncthreads();

        const float* Kph = sm + KH0 + cur*2048;
        const float* Kpl = sm + KL0 + cur*2048;
        const float* Vs  = sm + V0  + cur*2048;
        const float* Bp  = sm + BI0 + cur*8704;

        float acc_s[8][4];
        #pragma unroll
        for (int nt = 0; nt < 8; nt++)
            #pragma unroll
            for (int q = 0; q < 4; q++) acc_s[nt][q] = 0.f;

        #pragma unroll
        for (int ks = 0; ks < 4; ks++){
            int w0 = ks*8 + tig;
            uint32_t qhf[4], qlf[4];
            qhf[0] = *(const uint32_t*)&sm[QHo + rA0 + (w0 ^ swr)];
            qhf[1] = *(const uint32_t*)&sm[QHo + rA1 + (w0 ^ swr)];
            qhf[2] = *(const uint32_t*)&sm[QHo + rA0 + ((w0+4) ^ swr)];
            qhf[3] = *(const uint32_t*)&sm[QHo + rA1 + ((w0+4) ^ swr)];
            if (ks < 2){
                qlf[0] = *(const uint32_t*)&sm[QLo + rA0 + (w0 ^ swr)];
                qlf[1] = *(const uint32_t*)&sm[QLo + rA1 + (w0 ^ swr)];
                qlf[2] = *(const uint32_t*)&sm[QLo + rA0 + ((w0+4) ^ swr)];
                qlf[3] = *(const uint32_t*)&sm[QLo + rA1 + ((w0+4) ^ swr)];
            }
            #pragma unroll
            for (int nt = 0; nt < 8; nt++){
                int n = nt*8 + g;
                int ro = n*32, swn = (n&7) << 2;
                uint32_t khf[2];
                khf[0] = *(const uint32_t*)&Kph[ro + (w0 ^ swn)];
                khf[1] = *(const uint32_t*)&Kph[ro + ((w0+4) ^ swn)];
                mma16h(acc_s[nt], qhf, khf);
                if (ks < 2){
                    uint32_t klf[2];
                    klf[0] = *(const uint32_t*)&Kpl[ro + (w0 ^ swn)];
                    klf[1] = *(const uint32_t*)&Kpl[ro + ((w0+4) ^ swn)];
                    mma16h(acc_s[nt], qhf, klf);
                    mma16h(acc_s[nt], qlf, khf);
                }
            }
        }

        // ---- streaming softmax update (running max kept; p in [0,1]) ----
        float mx0 = acc_s[0][0], mx1 = acc_s[0][2];
        #pragma unroll
        for (int nt = 0; nt < 8; nt++){
            mx0 = fmaxf(mx0, fmaxf(acc_s[nt][0], acc_s[nt][1]));
            mx1 = fmaxf(mx1, fmaxf(acc_s[nt][2], acc_s[nt][3]));
        }
        #pragma unroll
        for (int o = 1; o < 4; o <<= 1){
            mx0 = fmaxf(mx0, __shfl_xor_sync(0xffffffffu, mx0, o));
            mx1 = fmaxf(mx1, __shfl_xor_sync(0xffffffffu, mx1, o));
        }
        float mn0 = fmaxf(mrow0, mx0);
        float mn1 = fmaxf(mrow1, mx1);
        float cr0 = __expf(mrow0 - mn0);
        float cr1 = __expf(mrow1 - mn1);
        mrow0 = mn0; mrow1 = mn1;
        lrow0 *= cr0; lrow1 *= cr1;
        #pragma unroll
        for (int nt = 0; nt < 8; nt++){
            acc_o[nt][0] *= cr0; acc_o[nt][1] *= cr0;
            acc_o[nt][2] *= cr1; acc_o[nt][3] *= cr1;
        }

        // exp, accumulate l (bias excluded), stage split-fp16 P*bias
        #pragma unroll
        for (int nt = 0; nt < 8; nt++){
            float p0 = __expf(acc_s[nt][0] - mn0);
            float p1 = __expf(acc_s[nt][1] - mn0);
            float p2 = __expf(acc_s[nt][2] - mn1);
            float p3 = __expf(acc_s[nt][3] - mn1);
            lrow0 += p0 + p1;
            lrow1 += p2 + p3;
            int col = nt*8 + tig*2;
            float2 b0 = *(const float2*)&Bp[r*68 + col];
            float2 b1 = *(const float2*)&Bp[(r+8)*68 + col];
            float v0 = p0*b0.x, v1 = p1*b0.y, v2 = p2*b1.x, v3 = p3*b1.y;
            __half h0,l0,h1,l1,h2,l2,h3,l3;
            split1h(v0,h0,l0); split1h(v1,h1,l1);
            split1h(v2,h2,l2); split1h(v3,h3,l3);
            int wc = (nt*4 + tig) ^ swr;
            *(uint32_t*)&sm[PHo + rA0 + wc] = pack2h(h0,h1);
            *(uint32_t*)&sm[PHo + rA1 + wc] = pack2h(h2,h3);
            *(uint32_t*)&sm[PLo + rA0 + wc] = pack2h(l0,l1);
            *(uint32_t*)&sm[PLo + rA1 + wc] = pack2h(l2,l3);
        }
        __syncwarp();

        // ---- O += P . V  (P 2-level, V single) ----
        #pragma unroll
        for (int ks = 0; ks < 4; ks++){
            int w0 = ks*8 + tig;
            uint32_t phf[4], plf[4];
            phf[0] = *(const uint32_t*)&sm[PHo + rA0 + (w0 ^ swr)];
            phf[1] = *(const uint32_t*)&sm[PHo + rA1 + (w0 ^ swr)];
            phf[2] = *(const uint32_t*)&sm[PHo + rA0 + ((w0+4) ^ swr)];
            phf[3] = *(const uint32_t*)&sm[PHo + rA1 + ((w0+4) ^ swr)];
            plf[0] = *(const uint32_t*)&sm[PLo + rA0 + (w0 ^ swr)];
            plf[1] = *(const uint32_t*)&sm[PLo + rA1 + (w0 ^ swr)];
            plf[2] = *(const uint32_t*)&sm[PLo + rA0 + ((w0+4) ^ swr)];
            plf[3] = *(const uint32_t*)&sm[PLo + rA1 + ((w0+4) ^ swr)];
            int base0 = w0*64, base1 = (w0+4)*64;
            int swv = tig << 3;
            #pragma unroll
            for (int nt = 0; nt < 8; nt++){
                int d = nt*8 + g;
                uint32_t vf[2];
                vf[0] = *(const uint32_t*)&Vs[base0 + (d ^ swv)];
                vf[1] = *(const uint32_t*)&Vs[base1 + (d ^ swv)];
                mma16h(acc_o[nt], phf, vf);
                mma16h(acc_o[nt], plf, vf);
            }
        }
        __syncthreads();
    }

    #pragma unroll
    for (int o = 1; o < 4; o <<= 1){
        lrow0 += __shfl_xor_sync(0xffffffffu, lrow0, o);
        lrow1 += __shfl_xor_sync(0xffffffffu, lrow1, o);
    }
    float inv0 = 1.f / lrow0, inv1 = 1.f / lrow1;
    int grow = m0 + r;
    #pragma unroll
    for (int nt = 0; nt < 8; nt++){
        int col = h*64 + nt*8 + tig*2;
        float o0 = acc_o[nt][0]*inv0, o1 = acc_o[nt][1]*inv0;
        float o2 = acc_o[nt][2]*inv1, o3 = acc_o[nt][3]*inv1;
        __nv_bfloat16 h0,l0,h1,l1,h2,l2,h3,l3;
        split1(o0,h0,l0); split1(o1,h1,l1);
        split1(o2,h2,l2); split1(o3,h3,l3);
        size_t off0 = ((size_t)(b*SS + grow    ))*HIDD + col;
        size_t off1 = ((size_t)(b*SS + grow + 8))*HIDD + col;
        *(uint32_t*)&Ch[off0] = pack2(h0,h1);
        *(uint32_t*)&Cl[off0] = pack2(l0,l1);
        *(uint32_t*)&Ch[off1] = pack2(h2,h3);
        *(uint32_t*)&Cl[off1] = pack2(l2,l3);
    }
}

// ---------------------------------------------------------------------------
extern "C" void kernel_launch(void* const* d_in, const int* in_sizes, int n_in,
                              void* d_out, int out_size)
{
    const float* x    = (const float*)d_in[0];
    const float* sinu = (const float*)d_in[1];
    const float* bias = (const float*)d_in[2];
    const float* Wq   = (const float*)d_in[3];
    const float* bq   = (const float*)d_in[4];
    const float* Wk   = (const float*)d_in[5];
    const float* bk   = (const float*)d_in[6];
    const float* Wv   = (const float*)d_in[7];
    const float* bv   = (const float*)d_in[8];
    const float* Wo   = (const float*)d_in[9];
    float* out = (float*)d_out;

    float *Q32, *K32, *V32, *Vp, *Wh, *Wl;
    __half *Qh, *Ql, *Kh, *Kl;
    __nv_bfloat16 *Ch, *Cl, *Xh, *Xl;
    cudaGetSymbolAddress((void**)&Q32, g_Q32);
    cudaGetSymbolAddress((void**)&K32, g_K32);
    cudaGetSymbolAddress((void**)&V32, g_V32);
    cudaGetSymbolAddress((void**)&Qh, g_Qh);  cudaGetSymbolAddress((void**)&Ql, g_Ql);
    cudaGetSymbolAddress((void**)&Kh, g_Kh);  cudaGetSymbolAddress((void**)&Kl, g_Kl);
    cudaGetSymbolAddress((void**)&Vp, g_Vp);
    cudaGetSymbolAddress((void**)&Ch, g_Ch);  cudaGetSymbolAddress((void**)&Cl, g_Cl);
    cudaGetSymbolAddress((void**)&Xh, g_Xh);  cudaGetSymbolAddress((void**)&Xl, g_Xl);
    cudaGetSymbolAddress((void**)&Wh, g_Wh);
    cudaGetSymbolAddress((void**)&Wl, g_Wl);
    const int WSTRIDE = (HIDD/2)*HIDD;

    cudaFuncSetAttribute(gemm_sb,    cudaFuncAttributeMaxDynamicSharedMemorySize, 73728);
    cudaFuncSetAttribute(flash_attn, cudaFuncAttributeMaxDynamicSharedMemorySize, 184320);

    // prep: splits
    split_x_k<<<(NELEM/2 + 255)/256, 256>>>((const float2*)x,
        (__nv_bfloat162*)Xh, (__nv_bfloat162*)Xl, NELEM/2);
    int nww = WSTRIDE;
    split_w_k<<<(nww + 255)/256, 256>>>(Wq, (uint32_t*)(Wh + 0*WSTRIDE), (uint32_t*)(Wl + 0*WSTRIDE));
    split_w_k<<<(nww + 255)/256, 256>>>(Wk, (uint32_t*)(Wh + 1*WSTRIDE), (uint32_t*)(Wl + 1*WSTRIDE));
    split_w_k<<<(nww + 255)/256, 256>>>(Wv, (uint32_t*)(Wh + 2*WSTRIDE), (uint32_t*)(Wl + 2*WSTRIDE));
    split_w_k<<<(nww + 255)/256, 256>>>(Wo, (uint32_t*)(Wh + 3*WSTRIDE), (uint32_t*)(Wl + 3*WSTRIDE));

    // projections
    dim3 gg(HIDD/128, MTOT/128);   // (8, 32)
    gemm_sb<<<gg, 256, 73728>>>(Xh, Xl, Wh + 0*WSTRIDE, Wl + 0*WSTRIDE, bq, Q32, MTOT, HIDD, HIDD, 1);
    gemm_sb<<<gg, 256, 73728>>>(Xh, Xl, Wh + 1*WSTRIDE, Wl + 1*WSTRIDE, bk, K32, MTOT, HIDD, HIDD, 1);
    gemm_sb<<<gg, 256, 73728>>>(Xh, Xl, Wh + 2*WSTRIDE, Wl + 2*WSTRIDE, bv, V32, MTOT, HIDD, HIDD, 1);

    // rotary + fp16 splits, V pairing
    rotary_split_k<<<(NELEM/2 + 255)/256, 256>>>(Q32, K32, sinu,
        (__half2*)Qh, (__half2*)Ql, (__half2*)Kh, (__half2*)Kl);
    prep_v_k<<<(NELEM/2 + 255)/256, 256>>>(V32, (uint32_t*)Vp);

    // fused attention (h fastest for bias L2 reuse)
    flash_attn<<<dim3(NH, SS/128, BB), 256, 184320>>>(Qh, Ql, Kh, Kl, Vp, bias, Ch, Cl);

    // output projection
    gemm_sb<<<gg, 256, 73728>>>(Ch, Cl, Wh + 3*WSTRIDE, Wl + 3*WSTRIDE, nullptr, out, MTOT, HIDD, HIDD, 0);
}

// round 9
// speedup vs baseline: 4.1632x; 1.0579x over previous
#include <cuda_runtime.h>
#include <cuda_bf16.h>
#include <cuda_fp16.h>
#include <math.h>
#include <stdint.h>

#define BB 2
#define SS 2048
#define HIDD 1024
#define NH 16
#define MTOT (BB*SS)          // 4096
#define NELEM (BB*SS*HIDD)    // 4194304

// ---------------- scratch (allocation-free rule: device globals, ~92MB) ------
__device__ __nv_bfloat16 g_Xh[NELEM], g_Xl[NELEM];
__device__ float g_Wh[4][(HIDD/2)*HIDD], g_Wl[4][(HIDD/2)*HIDD];  // k-paired words
__device__ __half g_Qh[NELEM], g_Ql[NELEM];
__device__ __half g_Kh[NELEM], g_Kl[NELEM];
__device__ float g_Vp[NELEM/2];                          // token-paired fp16x2 words
__device__ __nv_bfloat16 g_Ch[NELEM], g_Cl[NELEM];
__device__ float g_Fq[64*MTOT], g_Fk[64*MTOT];           // [d][token]

// ---------------- helpers ----------------
__device__ __forceinline__ uint32_t smem_u32(const void* p){
    return (uint32_t)__cvta_generic_to_shared(p);
}
__device__ __forceinline__ void cp16(uint32_t d, const void* s){
    asm volatile("cp.async.cg.shared.global [%0], [%1], 16;" :: "r"(d), "l"(s));
}
__device__ __forceinline__ void cp_commit(){ asm volatile("cp.async.commit_group;"); }
template<int N> __device__ __forceinline__ void cp_wait(){
    asm volatile("cp.async.wait_group %0;" :: "n"(N));
}
__device__ __forceinline__ void mma16(float* c, const uint32_t* a, const uint32_t* b){
    asm volatile(
        "mma.sync.aligned.m16n8k16.row.col.f32.bf16.bf16.f32 "
        "{%0,%1,%2,%3}, {%4,%5,%6,%7}, {%8,%9}, {%0,%1,%2,%3};"
        : "+f"(c[0]), "+f"(c[1]), "+f"(c[2]), "+f"(c[3])
        : "r"(a[0]), "r"(a[1]), "r"(a[2]), "r"(a[3]), "r"(b[0]), "r"(b[1]));
}
__device__ __forceinline__ void mma16h(float* c, const uint32_t* a, const uint32_t* b){
    asm volatile(
        "mma.sync.aligned.m16n8k16.row.col.f32.f16.f16.f32 "
        "{%0,%1,%2,%3}, {%4,%5,%6,%7}, {%8,%9}, {%0,%1,%2,%3};"
        : "+f"(c[0]), "+f"(c[1]), "+f"(c[2]), "+f"(c[3])
        : "r"(a[0]), "r"(a[1]), "r"(a[2]), "r"(a[3]), "r"(b[0]), "r"(b[1]));
}
__device__ __forceinline__ void split1(float x, __nv_bfloat16& h, __nv_bfloat16& l){
    h = __float2bfloat16_rn(x);
    l = __float2bfloat16_rn(x - __bfloat162float(h));
}
__device__ __forceinline__ void split1h(float x, __half& h, __half& l){
    h = __float2half_rn(x);
    l = __float2half_rn(x - __half2float(h));
}
__device__ __forceinline__ uint32_t pack2(__nv_bfloat16 a, __nv_bfloat16 b){
    __nv_bfloat162 t; t.x = a; t.y = b;
    return *(uint32_t*)&t;
}
__device__ __forceinline__ uint32_t pack2h(__half a, __half b){
    __half2 t; t.x = a; t.y = b;
    return *(uint32_t*)&t;
}

// ---------------- prep: split x into bf16 hi/lo (row-major) ----------------
__global__ void split_x_k(const float2* __restrict__ src,
                          __nv_bfloat162* __restrict__ h, __nv_bfloat162* __restrict__ l, int n)
{
    int i = blockIdx.x * blockDim.x + threadIdx.x;
    if (i >= n) return;
    float2 v = src[i];
    __nv_bfloat16 h0, l0, h1, l1;
    split1(v.x, h0, l0); split1(v.y, h1, l1);
    __nv_bfloat162 hh; hh.x = h0; hh.y = h1;
    __nv_bfloat162 ll; ll.x = l0; ll.y = l1;
    h[i] = hh; l[i] = ll;
}

// ---------------- prep: split W into k-paired bf16x2 words ----------------
__global__ void split_w_k(const float* __restrict__ W,
                          uint32_t* __restrict__ Wh, uint32_t* __restrict__ Wl)
{
    int i = blockIdx.x * blockDim.x + threadIdx.x;   // over 512*1024
    if (i >= (HIDD/2)*HIDD) return;
    int n = i & (HIDD-1), kp = i >> 10;
    float x0 = W[(size_t)(2*kp)  *HIDD + n];
    float x1 = W[(size_t)(2*kp+1)*HIDD + n];
    __nv_bfloat16 h0,l0,h1,l1;
    split1(x0,h0,l0); split1(x1,h1,l1);
    Wh[i] = pack2(h0,h1);
    Wl[i] = pack2(l0,l1);
}

// ---------------- prep: rotary factor tables F[d][token] ----------------
__global__ void factors_k(const float* __restrict__ sinu,
                          float* __restrict__ Fq, float* __restrict__ Fk)
{
    int i = blockIdx.x * blockDim.x + threadIdx.x;   // 64*4096
    if (i >= 64*MTOT) return;
    int tok = i & (MTOT-1), d = i >> 12;
    int s = tok & (SS-1), b = tok >> 11;
    float f = 1.f;
    if (d < 32){
        float sn = sinu[(((size_t)b*2 + 0)*SS + s)*32 + d];
        float cs = sinu[(((size_t)b*2 + 1)*SS + s)*32 + d];
        f = (d & 1) ? (cs + sn) : (cs - sn);
    }
    Fk[i] = f;
    Fq[i] = f * 0.125f;
}

// ---------------------------------------------------------------------------
// split-bf16 GEMM with fused epilogues. C = A @ W (+bias).
// MODE 0: Q/K  -> +bias, *F[d][token], fp16 hi/lo split to O1/O2 [token][1024]
// MODE 1: V    -> +bias, token-pair fp16x2 pack to O1 = Vp [b][kp][1024]
// MODE 2: OUT  -> fp32 store to O1
// ---------------------------------------------------------------------------
template<int MODE>
__global__ __launch_bounds__(256)
void gemm_sb(const __nv_bfloat16* __restrict__ Ah, const __nv_bfloat16* __restrict__ Al,
             const float* __restrict__ Bh, const float* __restrict__ Bl,
             const float* __restrict__ bias, const float* __restrict__ F,
             void* __restrict__ O1, void* __restrict__ O2)
{
    extern __shared__ float smg[];
    const int tid = threadIdx.x, lane = tid & 31, wid = tid >> 5;
    const int g = lane >> 2, tig = lane & 3;
    const int m0 = blockIdx.y * 128, n0 = blockIdx.x * 128;
    const int wm = (wid >> 2) * 64, wn = (wid & 3) * 32;
    const int N = HIDD, K = HIDD;

    float acc[4][4][4];
    #pragma unroll
    for (int i = 0; i < 4; i++)
        #pragma unroll
        for (int j = 0; j < 4; j++)
            #pragma unroll
            for (int r = 0; r < 4; r++) acc[i][j][r] = 0.f;

    auto loadA = [&](int k0, int st){
        #pragma unroll
        for (int half = 0; half < 2; half++){
            const __nv_bfloat16* S = half ? Al : Ah;
            float* D = smg + (st*2 + half) * 2560;
            #pragma unroll
            for (int i = 0; i < 2; i++){
                int idx = tid + i*256;
                int row = idx >> 2, gw = idx & 3;
                cp16(smem_u32(D + row*20 + gw*4),
                     S + (size_t)(m0+row)*K + k0 + gw*8);
            }
        }
    };
    auto loadB = [&](int k0, int st){
        int kp0 = k0 >> 1;
        #pragma unroll
        for (int half = 0; half < 2; half++){
            const float* S = half ? Bl : Bh;
            float* D = smg + 10240 + (st*2 + half) * 2048;
            #pragma unroll
            for (int i = 0; i < 2; i++){
                int idx = tid + i*256;
                int kp = idx >> 5, gn = idx & 31;
                cp16(smem_u32(D + kp*128 + ((gn ^ ((kp&3)<<1))<<2)),
                     S + (size_t)(kp0+kp)*N + n0 + gn*4);
            }
        }
    };

    loadA(0, 0); loadB(0, 0); cp_commit();
    const int KT = K >> 5;
    for (int kt = 0; kt < KT; kt++){
        int cur = kt & 1;
        if (kt + 1 < KT){
            loadA((kt+1) << 5, cur ^ 1);
            loadB((kt+1) << 5, cur ^ 1);
            cp_commit();
            cp_wait<1>();
        } else cp_wait<0>();
        __syncthreads();

        const float* Ah_s = smg + (cur*2    )*2560;
        const float* Al_s = smg + (cur*2 + 1)*2560;
        const float* Bh_s = smg + 10240 + (cur*2    )*2048;
        const float* Bl_s = smg + 10240 + (cur*2 + 1)*2048;

        #pragma unroll
        for (int ks = 0; ks < 2; ks++){
            uint32_t bh[4][2], bl[4][2];
            #pragma unroll
            for (int nt = 0; nt < 4; nt++){
                int kp = ks*8 + tig;
                int sx = (wn + nt*8 + g) ^ (tig << 3);
                bh[nt][0] = *(const uint32_t*)&Bh_s[kp*128 + sx];
                bh[nt][1] = *(const uint32_t*)&Bh_s[(kp+4)*128 + sx];
                bl[nt][0] = *(const uint32_t*)&Bl_s[kp*128 + sx];
                bl[nt][1] = *(const uint32_t*)&Bl_s[(kp+4)*128 + sx];
            }
            #pragma unroll
            for (int mt = 0; mt < 4; mt++){
                int r = wm + mt*16 + g;
                int w0 = ks*8 + tig;
                uint32_t ah[4], al[4];
                ah[0] = *(const uint32_t*)&Ah_s[r*20 + w0];
                ah[1] = *(const uint32_t*)&Ah_s[(r+8)*20 + w0];
                ah[2] = *(const uint32_t*)&Ah_s[r*20 + w0 + 4];
                ah[3] = *(const uint32_t*)&Ah_s[(r+8)*20 + w0 + 4];
                al[0] = *(const uint32_t*)&Al_s[r*20 + w0];
                al[1] = *(const uint32_t*)&Al_s[(r+8)*20 + w0];
                al[2] = *(const uint32_t*)&Al_s[r*20 + w0 + 4];
                al[3] = *(const uint32_t*)&Al_s[(r+8)*20 + w0 + 4];
                #pragma unroll
                for (int nt = 0; nt < 4; nt++){
                    mma16(acc[mt][nt], ah, bh[nt]);
                    mma16(acc[mt][nt], ah, bl[nt]);
                    mma16(acc[mt][nt], al, bh[nt]);
                }
            }
        }
        __syncthreads();
    }

    // ---- fused epilogues ----
    #pragma unroll
    for (int mt = 0; mt < 4; mt++)
        #pragma unroll
        for (int nt = 0; nt < 4; nt++){
            int row = m0 + wm + mt*16 + g;         // token
            int col = n0 + wn + nt*8 + tig*2;
            float v0 = acc[mt][nt][0], v1 = acc[mt][nt][1];
            float v2 = acc[mt][nt][2], v3 = acc[mt][nt][3];
            if (MODE != 2){
                float bx = bias[col], by = bias[col+1];
                v0 += bx; v1 += by; v2 += bx; v3 += by;
            }
            if (MODE == 0){
                int d = col & 63;
                v0 *= F[(size_t)d*MTOT + row];
                v1 *= F[(size_t)(d+1)*MTOT + row];
                v2 *= F[(size_t)d*MTOT + row + 8];
                v3 *= F[(size_t)(d+1)*MTOT + row + 8];
                __half h0,l0,h1,l1,h2,l2,h3,l3;
                split1h(v0,h0,l0); split1h(v1,h1,l1);
                split1h(v2,h2,l2); split1h(v3,h3,l3);
                size_t w0i = ((size_t)row*HIDD + col) >> 1;
                size_t w1i = ((size_t)(row+8)*HIDD + col) >> 1;
                ((uint32_t*)O1)[w0i] = pack2h(h0,h1);
                ((uint32_t*)O2)[w0i] = pack2h(l0,l1);
                ((uint32_t*)O1)[w1i] = pack2h(h2,h3);
                ((uint32_t*)O2)[w1i] = pack2h(l2,l3);
            } else if (MODE == 1){
                float p0 = __shfl_xor_sync(0xffffffffu, v0, 4);
                float p1 = __shfl_xor_sync(0xffffffffu, v1, 4);
                float p2 = __shfl_xor_sync(0xffffffffu, v2, 4);
                float p3 = __shfl_xor_sync(0xffffffffu, v3, 4);
                if ((lane & 4) == 0){                // even g -> even token
                    int bidx = row >> 11, s0 = row & (SS-1);
                    size_t r0 = (size_t)(bidx*(SS/2) + (s0 >> 1))*HIDD + col;
                    size_t r1 = (size_t)(bidx*(SS/2) + ((s0+8) >> 1))*HIDD + col;
                    ((uint32_t*)O1)[r0]   = pack2h(__float2half_rn(v0), __float2half_rn(p0));
                    ((uint32_t*)O1)[r0+1] = pack2h(__float2half_rn(v1), __float2half_rn(p1));
                    ((uint32_t*)O1)[r1]   = pack2h(__float2half_rn(v2), __float2half_rn(p2));
                    ((uint32_t*)O1)[r1+1] = pack2h(__float2half_rn(v3), __float2half_rn(p3));
                }
            } else {
                *(float2*)&((float*)O1)[(size_t)row*HIDD + col] = make_float2(v0, v1);
                *(float2*)&((float*)O1)[(size_t)(row+8)*HIDD + col] = make_float2(v2, v3);
            }
        }
}

// ---------------------------------------------------------------------------
// Fused flash attention, fp16 mma. 64 q-rows/CTA, 128 threads, smem 80KB
// (2 CTAs/SM). Bias via direct LDG prefetch (no smem staging).
// QK: rotary chunks split 3-mma, rest single; PV: P split, V single.
// ---------------------------------------------------------------------------
__global__ __launch_bounds__(128)
void flash_attn(const __half* __restrict__ Qh, const __half* __restrict__ Ql,
                const __half* __restrict__ Kh, const __half* __restrict__ Kl,
                const float* __restrict__ Vp, const float* __restrict__ bias,
                __nv_bfloat16* __restrict__ Ch, __nv_bfloat16* __restrict__ Cl)
{
    extern __shared__ float sm[];
    const int QHo = 0, QLo = 2048;
    const int KH0 = 4096, KL0 = 8192;     // + st*2048
    const int V0  = 12288;                 // + st*2048
    const int PHo = 16384, PLo = 18432;    // total 20480 floats = 80KB

    const int tid = threadIdx.x, lane = tid & 31, wid = tid >> 5;
    const int g = lane >> 2, tig = lane & 3;
    const int h = blockIdx.x, m0 = blockIdx.y * 64, b = blockIdx.z;

    const __half* Qhg = Qh + ((size_t)(b*SS + m0))*HIDD + h*64;
    const __half* Qlg = Ql + ((size_t)(b*SS + m0))*HIDD + h*64;

    // Q tile once: 64 rows x 8 granules x 2 arrays = 1024 cp16
    #pragma unroll
    for (int i = 0; i < 8; i++){
        int idx = tid + i*128;
        int half = idx >> 9, rem = idx & 511;
        int row = rem >> 3, gw = rem & 7;
        int dst = row*32 + ((gw ^ (row&7)) << 2);
        cp16(smem_u32(sm + (half ? QLo : QHo) + dst),
             (half ? Qlg : Qhg) + (size_t)row*HIDD + gw*8);
    }

    auto load_tile = [&](int kt, int st){
        const __half* khg = Kh + ((size_t)(b*SS + kt*64))*HIDD + h*64;
        const __half* klg = Kl + ((size_t)(b*SS + kt*64))*HIDD + h*64;
        #pragma unroll
        for (int i = 0; i < 8; i++){
            int idx = tid + i*128;
            int half = idx >> 9, rem = idx & 511;
            int row = rem >> 3, gw = rem & 7;
            int dst = row*32 + ((gw ^ (row&7)) << 2);
            cp16(smem_u32(sm + (half ? KL0 : KH0) + st*2048 + dst),
                 (half ? klg : khg) + (size_t)row*HIDD + gw*8);
        }
        const float* vg = Vp + ((size_t)(b*(SS/2) + kt*32))*HIDD + h*64;
        #pragma unroll
        for (int i = 0; i < 4; i++){
            int idx = tid + i*128;
            int kp = idx >> 4, gw = idx & 15;
            int dst = kp*64 + ((gw ^ ((kp&3)<<1)) << 2);
            cp16(smem_u32(sm + V0 + st*2048 + dst), vg + (size_t)kp*HIDD + gw*4);
        }
    };

    load_tile(0, 0); cp_commit();

    float acc_o[8][4];
    #pragma unroll
    for (int nt = 0; nt < 8; nt++)
        #pragma unroll
        for (int r = 0; r < 4; r++) acc_o[nt][r] = 0.f;
    float mrow0 = -1e30f, mrow1 = -1e30f;
    float lrow0 = 0.f, lrow1 = 0.f;

    const int r   = wid*16 + g;            // 0..63
    const int swr = g << 2;
    const int rA0 = r*32, rA1 = (r+8)*32;
    const float* brow0 = bias + ((size_t)(b*SS + m0 + r))*SS;
    const float* brow1 = brow0 + (size_t)8*SS;

    for (int kt = 0; kt < SS/64; kt++){
        int cur = kt & 1;
        // bias prefetch for this tile (LDG, covered by QK mma latency)
        float2 bpre0[8], bpre1[8];
        #pragma unroll
        for (int nt = 0; nt < 8; nt++){
            bpre0[nt] = *(const float2*)&brow0[kt*64 + nt*8 + tig*2];
            bpre1[nt] = *(const float2*)&brow1[kt*64 + nt*8 + tig*2];
        }
        if (kt + 1 < SS/64){ load_tile(kt+1, cur^1); cp_commit(); cp_wait<1>(); }
        else cp_wait<0>();
        __syncthreads();

        const float* Kph = sm + KH0 + cur*2048;
        const float* Kpl = sm + KL0 + cur*2048;
        const float* Vs  = sm + V0  + cur*2048;

        float acc_s[8][4];
        #pragma unroll
        for (int nt = 0; nt < 8; nt++)
            #pragma unroll
            for (int q = 0; q < 4; q++) acc_s[nt][q] = 0.f;

        #pragma unroll
        for (int ks = 0; ks < 4; ks++){
            int w0 = ks*8 + tig;
            uint32_t qhf[4], qlf[4];
            qhf[0] = *(const uint32_t*)&sm[QHo + rA0 + (w0 ^ swr)];
            qhf[1] = *(const uint32_t*)&sm[QHo + rA1 + (w0 ^ swr)];
            qhf[2] = *(const uint32_t*)&sm[QHo + rA0 + ((w0+4) ^ swr)];
            qhf[3] = *(const uint32_t*)&sm[QHo + rA1 + ((w0+4) ^ swr)];
            if (ks < 2){
                qlf[0] = *(const uint32_t*)&sm[QLo + rA0 + (w0 ^ swr)];
                qlf[1] = *(const uint32_t*)&sm[QLo + rA1 + (w0 ^ swr)];
                qlf[2] = *(const uint32_t*)&sm[QLo + rA0 + ((w0+4) ^ swr)];
                qlf[3] = *(const uint32_t*)&sm[QLo + rA1 + ((w0+4) ^ swr)];
            }
            #pragma unroll
            for (int nt = 0; nt < 8; nt++){
                int n = nt*8 + g;
                int ro = n*32, swn = (n&7) << 2;
                uint32_t khf[2];
                khf[0] = *(const uint32_t*)&Kph[ro + (w0 ^ swn)];
                khf[1] = *(const uint32_t*)&Kph[ro + ((w0+4) ^ swn)];
                mma16h(acc_s[nt], qhf, khf);
                if (ks < 2){
                    uint32_t klf[2];
                    klf[0] = *(const uint32_t*)&Kpl[ro + (w0 ^ swn)];
                    klf[1] = *(const uint32_t*)&Kpl[ro + ((w0+4) ^ swn)];
                    mma16h(acc_s[nt], qhf, klf);
                    mma16h(acc_s[nt], qlf, khf);
                }
            }
        }

        // ---- streaming softmax update ----
        float mx0 = acc_s[0][0], mx1 = acc_s[0][2];
        #pragma unroll
        for (int nt = 0; nt < 8; nt++){
            mx0 = fmaxf(mx0, fmaxf(acc_s[nt][0], acc_s[nt][1]));
            mx1 = fmaxf(mx1, fmaxf(acc_s[nt][2], acc_s[nt][3]));
        }
        #pragma unroll
        for (int o = 1; o < 4; o <<= 1){
            mx0 = fmaxf(mx0, __shfl_xor_sync(0xffffffffu, mx0, o));
            mx1 = fmaxf(mx1, __shfl_xor_sync(0xffffffffu, mx1, o));
        }
        float mn0 = fmaxf(mrow0, mx0);
        float mn1 = fmaxf(mrow1, mx1);
        float cr0 = __expf(mrow0 - mn0);
        float cr1 = __expf(mrow1 - mn1);
        mrow0 = mn0; mrow1 = mn1;
        lrow0 *= cr0; lrow1 *= cr1;
        #pragma unroll
        for (int nt = 0; nt < 8; nt++){
            acc_o[nt][0] *= cr0; acc_o[nt][1] *= cr0;
            acc_o[nt][2] *= cr1; acc_o[nt][3] *= cr1;
        }

        // exp, accumulate l (bias excluded), stage split-fp16 P*bias
        #pragma unroll
        for (int nt = 0; nt < 8; nt++){
            float p0 = __expf(acc_s[nt][0] - mn0);
            float p1 = __expf(acc_s[nt][1] - mn0);
            float p2 = __expf(acc_s[nt][2] - mn1);
            float p3 = __expf(acc_s[nt][3] - mn1);
            lrow0 += p0 + p1;
            lrow1 += p2 + p3;
            float v0 = p0*bpre0[nt].x, v1 = p1*bpre0[nt].y;
            float v2 = p2*bpre1[nt].x, v3 = p3*bpre1[nt].y;
            __half h0,l0,h1,l1,h2,l2,h3,l3;
            split1h(v0,h0,l0); split1h(v1,h1,l1);
            split1h(v2,h2,l2); split1h(v3,h3,l3);
            int wc = (nt*4 + tig) ^ swr;
            *(uint32_t*)&sm[PHo + rA0 + wc] = pack2h(h0,h1);
            *(uint32_t*)&sm[PHo + rA1 + wc] = pack2h(h2,h3);
            *(uint32_t*)&sm[PLo + rA0 + wc] = pack2h(l0,l1);
            *(uint32_t*)&sm[PLo + rA1 + wc] = pack2h(l2,l3);
        }
        __syncwarp();

        // ---- O += P . V  (P 2-level, V single) ----
        #pragma unroll
        for (int ks = 0; ks < 4; ks++){
            int w0 = ks*8 + tig;
            uint32_t phf[4], plf[4];
            phf[0] = *(const uint32_t*)&sm[PHo + rA0 + (w0 ^ swr)];
            phf[1] = *(const uint32_t*)&sm[PHo + rA1 + (w0 ^ swr)];
            phf[2] = *(const uint32_t*)&sm[PHo + rA0 + ((w0+4) ^ swr)];
            phf[3] = *(const uint32_t*)&sm[PHo + rA1 + ((w0+4) ^ swr)];
            plf[0] = *(const uint32_t*)&sm[PLo + rA0 + (w0 ^ swr)];
            plf[1] = *(const uint32_t*)&sm[PLo + rA1 + (w0 ^ swr)];
            plf[2] = *(const uint32_t*)&sm[PLo + rA0 + ((w0+4) ^ swr)];
            plf[3] = *(const uint32_t*)&sm[PLo + rA1 + ((w0+4) ^ swr)];
            int base0 = w0*64, base1 = (w0+4)*64;
            int swv = tig << 3;
            #pragma unroll
            for (int nt = 0; nt < 8; nt++){
                int d = nt*8 + g;
                uint32_t vf[2];
                vf[0] = *(const uint32_t*)&Vs[base0 + (d ^ swv)];
                vf[1] = *(const uint32_t*)&Vs[base1 + (d ^ swv)];
                mma16h(acc_o[nt], phf, vf);
                mma16h(acc_o[nt], plf, vf);
            }
        }
        __syncthreads();
    }

    #pragma unroll
    for (int o = 1; o < 4; o <<= 1){
        lrow0 += __shfl_xor_sync(0xffffffffu, lrow0, o);
        lrow1 += __shfl_xor_sync(0xffffffffu, lrow1, o);
    }
    float inv0 = 1.f / lrow0, inv1 = 1.f / lrow1;
    int grow = m0 + r;
    #pragma unroll
    for (int nt = 0; nt < 8; nt++){
        int col = h*64 + nt*8 + tig*2;
        float o0 = acc_o[nt][0]*inv0, o1 = acc_o[nt][1]*inv0;
        float o2 = acc_o[nt][2]*inv1, o3 = acc_o[nt][3]*inv1;
        __nv_bfloat16 h0,l0,h1,l1,h2,l2,h3,l3;
        split1(o0,h0,l0); split1(o1,h1,l1);
        split1(o2,h2,l2); split1(o3,h3,l3);
        size_t off0 = ((size_t)(b*SS + grow    ))*HIDD + col;
        size_t off1 = ((size_t)(b*SS + grow + 8))*HIDD + col;
        *(uint32_t*)&Ch[off0] = pack2(h0,h1);
        *(uint32_t*)&Cl[off0] = pack2(l0,l1);
        *(uint32_t*)&Ch[off1] = pack2(h2,h3);
        *(uint32_t*)&Cl[off1] = pack2(l2,l3);
    }
}

// ---------------------------------------------------------------------------
extern "C" void kernel_launch(void* const* d_in, const int* in_sizes, int n_in,
                              void* d_out, int out_size)
{
    const float* x    = (const float*)d_in[0];
    const float* sinu = (const float*)d_in[1];
    const float* bias = (const float*)d_in[2];
    const float* Wq   = (const float*)d_in[3];
    const float* bq   = (const float*)d_in[4];
    const float* Wk   = (const float*)d_in[5];
    const float* bk   = (const float*)d_in[6];
    const float* Wv   = (const float*)d_in[7];
    const float* bv   = (const float*)d_in[8];
    const float* Wo   = (const float*)d_in[9];
    float* out = (float*)d_out;

    float *Vp, *Wh, *Wl, *Fq, *Fk;
    __half *Qh, *Ql, *Kh, *Kl;
    __nv_bfloat16 *Ch, *Cl, *Xh, *Xl;
    cudaGetSymbolAddress((void**)&Qh, g_Qh);  cudaGetSymbolAddress((void**)&Ql, g_Ql);
    cudaGetSymbolAddress((void**)&Kh, g_Kh);  cudaGetSymbolAddress((void**)&Kl, g_Kl);
    cudaGetSymbolAddress((void**)&Vp, g_Vp);
    cudaGetSymbolAddress((void**)&Ch, g_Ch);  cudaGetSymbolAddress((void**)&Cl, g_Cl);
    cudaGetSymbolAddress((void**)&Xh, g_Xh);  cudaGetSymbolAddress((void**)&Xl, g_Xl);
    cudaGetSymbolAddress((void**)&Wh, g_Wh);  cudaGetSymbolAddress((void**)&Wl, g_Wl);
    cudaGetSymbolAddress((void**)&Fq, g_Fq);  cudaGetSymbolAddress((void**)&Fk, g_Fk);
    const int WSTRIDE = (HIDD/2)*HIDD;

    cudaFuncSetAttribute(gemm_sb<0>, cudaFuncAttributeMaxDynamicSharedMemorySize, 73728);
    cudaFuncSetAttribute(gemm_sb<1>, cudaFuncAttributeMaxDynamicSharedMemorySize, 73728);
    cudaFuncSetAttribute(gemm_sb<2>, cudaFuncAttributeMaxDynamicSharedMemorySize, 73728);
    cudaFuncSetAttribute(flash_attn, cudaFuncAttributeMaxDynamicSharedMemorySize, 81920);
    cudaFuncSetAttribute(flash_attn, cudaFuncAttributePreferredSharedMemoryCarveout, 100);

    // prep
    split_x_k<<<(NELEM/2 + 255)/256, 256>>>((const float2*)x,
        (__nv_bfloat162*)Xh, (__nv_bfloat162*)Xl, NELEM/2);
    split_w_k<<<(WSTRIDE + 255)/256, 256>>>(Wq, (uint32_t*)(Wh + 0*WSTRIDE), (uint32_t*)(Wl + 0*WSTRIDE));
    split_w_k<<<(WSTRIDE + 255)/256, 256>>>(Wk, (uint32_t*)(Wh + 1*WSTRIDE), (uint32_t*)(Wl + 1*WSTRIDE));
    split_w_k<<<(WSTRIDE + 255)/256, 256>>>(Wv, (uint32_t*)(Wh + 2*WSTRIDE), (uint32_t*)(Wl + 2*WSTRIDE));
    split_w_k<<<(WSTRIDE + 255)/256, 256>>>(Wo, (uint32_t*)(Wh + 3*WSTRIDE), (uint32_t*)(Wl + 3*WSTRIDE));
    factors_k<<<(64*MTOT + 255)/256, 256>>>(sinu, Fq, Fk);

    // projections with fused epilogues
    dim3 gg(HIDD/128, MTOT/128);   // (8, 32)
    gemm_sb<0><<<gg, 256, 73728>>>(Xh, Xl, Wh + 0*WSTRIDE, Wl + 0*WSTRIDE, bq, Fq, Qh, Ql);
    gemm_sb<0><<<gg, 256, 73728>>>(Xh, Xl, Wh + 1*WSTRIDE, Wl + 1*WSTRIDE, bk, Fk, Kh, Kl);
    gemm_sb<1><<<gg, 256, 73728>>>(Xh, Xl, Wh + 2*WSTRIDE, Wl + 2*WSTRIDE, bv, nullptr, Vp, nullptr);

    // fused attention: 64-row q tiles, h fastest for bias L2 reuse
    flash_attn<<<dim3(NH, SS/64, BB), 128, 81920>>>(Qh, Ql, Kh, Kl, Vp, bias, Ch, Cl);

    // output projection
    gemm_sb<2><<<gg, 256, 73728>>>(Ch, Cl, Wh + 3*WSTRIDE, Wl + 3*WSTRIDE, nullptr, nullptr, out, nullptr);
}

// round 10
// speedup vs baseline: 4.4001x; 1.0569x over previous
#include <cuda_runtime.h>
#include <cuda_bf16.h>
#include <cuda_fp16.h>
#include <math.h>
#include <stdint.h>

#define BB 2
#define SS 2048
#define HIDD 1024
#define NH 16
#define MTOT (BB*SS)          // 4096
#define NELEM (BB*SS*HIDD)    // 4194304

// ---------------- scratch (allocation-free rule: device globals, ~92MB) ------
__device__ __nv_bfloat16 g_Xh[NELEM], g_Xl[NELEM];
__device__ float g_Wh[4][(HIDD/2)*HIDD], g_Wl[4][(HIDD/2)*HIDD];  // k-paired words
__device__ __half g_Qh[NELEM], g_Ql[NELEM];
__device__ __half g_Kh[NELEM], g_Kl[NELEM];
__device__ float g_Vp[NELEM/2];                          // token-paired fp16x2 words
__device__ __nv_bfloat16 g_Ch[NELEM], g_Cl[NELEM];
__device__ float g_Fq[64*MTOT], g_Fk[64*MTOT];           // [d][token]

// ---------------- helpers ----------------
__device__ __forceinline__ uint32_t smem_u32(const void* p){
    return (uint32_t)__cvta_generic_to_shared(p);
}
__device__ __forceinline__ void cp16(uint32_t d, const void* s){
    asm volatile("cp.async.cg.shared.global [%0], [%1], 16;" :: "r"(d), "l"(s));
}
__device__ __forceinline__ void cp_commit(){ asm volatile("cp.async.commit_group;"); }
template<int N> __device__ __forceinline__ void cp_wait(){
    asm volatile("cp.async.wait_group %0;" :: "n"(N));
}
__device__ __forceinline__ void mma16(float* c, const uint32_t* a, const uint32_t* b){
    asm volatile(
        "mma.sync.aligned.m16n8k16.row.col.f32.bf16.bf16.f32 "
        "{%0,%1,%2,%3}, {%4,%5,%6,%7}, {%8,%9}, {%0,%1,%2,%3};"
        : "+f"(c[0]), "+f"(c[1]), "+f"(c[2]), "+f"(c[3])
        : "r"(a[0]), "r"(a[1]), "r"(a[2]), "r"(a[3]), "r"(b[0]), "r"(b[1]));
}
__device__ __forceinline__ void mma16h(float* c, const uint32_t* a, const uint32_t* b){
    asm volatile(
        "mma.sync.aligned.m16n8k16.row.col.f32.f16.f16.f32 "
        "{%0,%1,%2,%3}, {%4,%5,%6,%7}, {%8,%9}, {%0,%1,%2,%3};"
        : "+f"(c[0]), "+f"(c[1]), "+f"(c[2]), "+f"(c[3])
        : "r"(a[0]), "r"(a[1]), "r"(a[2]), "r"(a[3]), "r"(b[0]), "r"(b[1]));
}
__device__ __forceinline__ void split1(float x, __nv_bfloat16& h, __nv_bfloat16& l){
    h = __float2bfloat16_rn(x);
    l = __float2bfloat16_rn(x - __bfloat162float(h));
}
__device__ __forceinline__ void split1h(float x, __half& h, __half& l){
    h = __float2half_rn(x);
    l = __float2half_rn(x - __half2float(h));
}
__device__ __forceinline__ uint32_t pack2(__nv_bfloat16 a, __nv_bfloat16 b){
    __nv_bfloat162 t; t.x = a; t.y = b;
    return *(uint32_t*)&t;
}
__device__ __forceinline__ uint32_t pack2h(__half a, __half b){
    __half2 t; t.x = a; t.y = b;
    return *(uint32_t*)&t;
}

// ---------------- prep: split x into bf16 hi/lo (row-major) ----------------
__global__ void split_x_k(const float2* __restrict__ src,
                          __nv_bfloat162* __restrict__ h, __nv_bfloat162* __restrict__ l, int n)
{
    int i = blockIdx.x * blockDim.x + threadIdx.x;
    if (i >= n) return;
    float2 v = src[i];
    __nv_bfloat16 h0, l0, h1, l1;
    split1(v.x, h0, l0); split1(v.y, h1, l1);
    __nv_bfloat162 hh; hh.x = h0; hh.y = h1;
    __nv_bfloat162 ll; ll.x = l0; ll.y = l1;
    h[i] = hh; l[i] = ll;
}

// ---------------- prep: split W into k-paired bf16x2 words ----------------
__global__ void split_w_k(const float* __restrict__ W,
                          uint32_t* __restrict__ Wh, uint32_t* __restrict__ Wl)
{
    int i = blockIdx.x * blockDim.x + threadIdx.x;   // over 512*1024
    if (i >= (HIDD/2)*HIDD) return;
    int n = i & (HIDD-1), kp = i >> 10;
    float x0 = W[(size_t)(2*kp)  *HIDD + n];
    float x1 = W[(size_t)(2*kp+1)*HIDD + n];
    __nv_bfloat16 h0,l0,h1,l1;
    split1(x0,h0,l0); split1(x1,h1,l1);
    Wh[i] = pack2(h0,h1);
    Wl[i] = pack2(l0,l1);
}

// ---------------- prep: rotary factor tables F[d][token] ----------------
__global__ void factors_k(const float* __restrict__ sinu,
                          float* __restrict__ Fq, float* __restrict__ Fk)
{
    int i = blockIdx.x * blockDim.x + threadIdx.x;   // 64*4096
    if (i >= 64*MTOT) return;
    int tok = i & (MTOT-1), d = i >> 12;
    int s = tok & (SS-1), b = tok >> 11;
    float f = 1.f;
    if (d < 32){
        float sn = sinu[(((size_t)b*2 + 0)*SS + s)*32 + d];
        float cs = sinu[(((size_t)b*2 + 1)*SS + s)*32 + d];
        f = (d & 1) ? (cs + sn) : (cs - sn);
    }
    Fk[i] = f;
    Fq[i] = f * 0.125f;
}

// ---------------------------------------------------------------------------
// split-bf16 GEMM with fused epilogues. C = A @ W (+bias).
// MODE 0: Q/K  -> +bias, *F[d][token], fp16 hi/lo split to O1/O2 [token][1024]
// MODE 1: V    -> +bias, token-pair fp16x2 pack to O1 = Vp [b][kp][1024]
// MODE 2: OUT  -> fp32 store to O1
// ---------------------------------------------------------------------------
template<int MODE>
__global__ __launch_bounds__(256)
void gemm_sb(const __nv_bfloat16* __restrict__ Ah, const __nv_bfloat16* __restrict__ Al,
             const float* __restrict__ Bh, const float* __restrict__ Bl,
             const float* __restrict__ bias, const float* __restrict__ F,
             void* __restrict__ O1, void* __restrict__ O2)
{
    extern __shared__ float smg[];
    const int tid = threadIdx.x, lane = tid & 31, wid = tid >> 5;
    const int g = lane >> 2, tig = lane & 3;
    const int m0 = blockIdx.y * 128, n0 = blockIdx.x * 128;
    const int wm = (wid >> 2) * 64, wn = (wid & 3) * 32;
    const int N = HIDD, K = HIDD;

    float acc[4][4][4];
    #pragma unroll
    for (int i = 0; i < 4; i++)
        #pragma unroll
        for (int j = 0; j < 4; j++)
            #pragma unroll
            for (int r = 0; r < 4; r++) acc[i][j][r] = 0.f;

    auto loadA = [&](int k0, int st){
        #pragma unroll
        for (int half = 0; half < 2; half++){
            const __nv_bfloat16* S = half ? Al : Ah;
            float* D = smg + (st*2 + half) * 2560;
            #pragma unroll
            for (int i = 0; i < 2; i++){
                int idx = tid + i*256;
                int row = idx >> 2, gw = idx & 3;
                cp16(smem_u32(D + row*20 + gw*4),
                     S + (size_t)(m0+row)*K + k0 + gw*8);
            }
        }
    };
    auto loadB = [&](int k0, int st){
        int kp0 = k0 >> 1;
        #pragma unroll
        for (int half = 0; half < 2; half++){
            const float* S = half ? Bl : Bh;
            float* D = smg + 10240 + (st*2 + half) * 2048;
            #pragma unroll
            for (int i = 0; i < 2; i++){
                int idx = tid + i*256;
                int kp = idx >> 5, gn = idx & 31;
                cp16(smem_u32(D + kp*128 + ((gn ^ ((kp&3)<<1))<<2)),
                     S + (size_t)(kp0+kp)*N + n0 + gn*4);
            }
        }
    };

    loadA(0, 0); loadB(0, 0); cp_commit();
    const int KT = K >> 5;
    for (int kt = 0; kt < KT; kt++){
        int cur = kt & 1;
        if (kt + 1 < KT){
            loadA((kt+1) << 5, cur ^ 1);
            loadB((kt+1) << 5, cur ^ 1);
            cp_commit();
            cp_wait<1>();
        } else cp_wait<0>();
        __syncthreads();

        const float* Ah_s = smg + (cur*2    )*2560;
        const float* Al_s = smg + (cur*2 + 1)*2560;
        const float* Bh_s = smg + 10240 + (cur*2    )*2048;
        const float* Bl_s = smg + 10240 + (cur*2 + 1)*2048;

        #pragma unroll
        for (int ks = 0; ks < 2; ks++){
            uint32_t bh[4][2], bl[4][2];
            #pragma unroll
            for (int nt = 0; nt < 4; nt++){
                int kp = ks*8 + tig;
                int sx = (wn + nt*8 + g) ^ (tig << 3);
                bh[nt][0] = *(const uint32_t*)&Bh_s[kp*128 + sx];
                bh[nt][1] = *(const uint32_t*)&Bh_s[(kp+4)*128 + sx];
                bl[nt][0] = *(const uint32_t*)&Bl_s[kp*128 + sx];
                bl[nt][1] = *(const uint32_t*)&Bl_s[(kp+4)*128 + sx];
            }
            #pragma unroll
            for (int mt = 0; mt < 4; mt++){
                int r = wm + mt*16 + g;
                int w0 = ks*8 + tig;
                uint32_t ah[4], al[4];
                ah[0] = *(const uint32_t*)&Ah_s[r*20 + w0];
                ah[1] = *(const uint32_t*)&Ah_s[(r+8)*20 + w0];
                ah[2] = *(const uint32_t*)&Ah_s[r*20 + w0 + 4];
                ah[3] = *(const uint32_t*)&Ah_s[(r+8)*20 + w0 + 4];
                al[0] = *(const uint32_t*)&Al_s[r*20 + w0];
                al[1] = *(const uint32_t*)&Al_s[(r+8)*20 + w0];
                al[2] = *(const uint32_t*)&Al_s[r*20 + w0 + 4];
                al[3] = *(const uint32_t*)&Al_s[(r+8)*20 + w0 + 4];
                #pragma unroll
                for (int nt = 0; nt < 4; nt++){
                    mma16(acc[mt][nt], ah, bh[nt]);
                    mma16(acc[mt][nt], ah, bl[nt]);
                    mma16(acc[mt][nt], al, bh[nt]);
                }
            }
        }
        __syncthreads();
    }

    // ---- fused epilogues ----
    #pragma unroll
    for (int mt = 0; mt < 4; mt++)
        #pragma unroll
        for (int nt = 0; nt < 4; nt++){
            int row = m0 + wm + mt*16 + g;         // token
            int col = n0 + wn + nt*8 + tig*2;
            float v0 = acc[mt][nt][0], v1 = acc[mt][nt][1];
            float v2 = acc[mt][nt][2], v3 = acc[mt][nt][3];
            if (MODE != 2){
                float bx = bias[col], by = bias[col+1];
                v0 += bx; v1 += by; v2 += bx; v3 += by;
            }
            if (MODE == 0){
                int d = col & 63;
                v0 *= F[(size_t)d*MTOT + row];
                v1 *= F[(size_t)(d+1)*MTOT + row];
                v2 *= F[(size_t)d*MTOT + row + 8];
                v3 *= F[(size_t)(d+1)*MTOT + row + 8];
                __half h0,l0,h1,l1,h2,l2,h3,l3;
                split1h(v0,h0,l0); split1h(v1,h1,l1);
                split1h(v2,h2,l2); split1h(v3,h3,l3);
                size_t w0i = ((size_t)row*HIDD + col) >> 1;
                size_t w1i = ((size_t)(row+8)*HIDD + col) >> 1;
                ((uint32_t*)O1)[w0i] = pack2h(h0,h1);
                ((uint32_t*)O2)[w0i] = pack2h(l0,l1);
                ((uint32_t*)O1)[w1i] = pack2h(h2,h3);
                ((uint32_t*)O2)[w1i] = pack2h(l2,l3);
            } else if (MODE == 1){
                float p0 = __shfl_xor_sync(0xffffffffu, v0, 4);
                float p1 = __shfl_xor_sync(0xffffffffu, v1, 4);
                float p2 = __shfl_xor_sync(0xffffffffu, v2, 4);
                float p3 = __shfl_xor_sync(0xffffffffu, v3, 4);
                if ((lane & 4) == 0){                // even g -> even token
                    int bidx = row >> 11, s0 = row & (SS-1);
                    size_t r0 = (size_t)(bidx*(SS/2) + (s0 >> 1))*HIDD + col;
                    size_t r1 = (size_t)(bidx*(SS/2) + ((s0+8) >> 1))*HIDD + col;
                    ((uint32_t*)O1)[r0]   = pack2h(__float2half_rn(v0), __float2half_rn(p0));
                    ((uint32_t*)O1)[r0+1] = pack2h(__float2half_rn(v1), __float2half_rn(p1));
                    ((uint32_t*)O1)[r1]   = pack2h(__float2half_rn(v2), __float2half_rn(p2));
                    ((uint32_t*)O1)[r1+1] = pack2h(__float2half_rn(v3), __float2half_rn(p3));
                }
            } else {
                *(float2*)&((float*)O1)[(size_t)row*HIDD + col] = make_float2(v0, v1);
                *(float2*)&((float*)O1)[(size_t)(row+8)*HIDD + col] = make_float2(v2, v3);
            }
        }
}

// ---------------------------------------------------------------------------
// Fused flash attention, fp16 mma. 64 q-rows/CTA, 128 threads, smem 72KB.
// Bias via direct LDG prefetch. QK: rotary chunks 3-mma split, rest single.
// PV: P single fp16 x V single fp16 (1 mma per pair).
// ---------------------------------------------------------------------------
__global__ __launch_bounds__(128)
void flash_attn(const __half* __restrict__ Qh, const __half* __restrict__ Ql,
                const __half* __restrict__ Kh, const __half* __restrict__ Kl,
                const float* __restrict__ Vp, const float* __restrict__ bias,
                __nv_bfloat16* __restrict__ Ch, __nv_bfloat16* __restrict__ Cl)
{
    extern __shared__ float sm[];
    const int QHo = 0, QLo = 2048;
    const int KH0 = 4096, KL0 = 8192;     // + st*2048
    const int V0  = 12288;                 // + st*2048
    const int PHo = 16384;                 // total 18432 floats = 72KB

    const int tid = threadIdx.x, lane = tid & 31, wid = tid >> 5;
    const int g = lane >> 2, tig = lane & 3;
    const int h = blockIdx.x, m0 = blockIdx.y * 64, b = blockIdx.z;

    const __half* Qhg = Qh + ((size_t)(b*SS + m0))*HIDD + h*64;
    const __half* Qlg = Ql + ((size_t)(b*SS + m0))*HIDD + h*64;

    // Q tile once: 64 rows x 8 granules x 2 arrays = 1024 cp16
    #pragma unroll
    for (int i = 0; i < 8; i++){
        int idx = tid + i*128;
        int half = idx >> 9, rem = idx & 511;
        int row = rem >> 3, gw = rem & 7;
        int dst = row*32 + ((gw ^ (row&7)) << 2);
        cp16(smem_u32(sm + (half ? QLo : QHo) + dst),
             (half ? Qlg : Qhg) + (size_t)row*HIDD + gw*8);
    }

    auto load_tile = [&](int kt, int st){
        const __half* khg = Kh + ((size_t)(b*SS + kt*64))*HIDD + h*64;
        const __half* klg = Kl + ((size_t)(b*SS + kt*64))*HIDD + h*64;
        #pragma unroll
        for (int i = 0; i < 8; i++){
            int idx = tid + i*128;
            int half = idx >> 9, rem = idx & 511;
            int row = rem >> 3, gw = rem & 7;
            int dst = row*32 + ((gw ^ (row&7)) << 2);
            cp16(smem_u32(sm + (half ? KL0 : KH0) + st*2048 + dst),
                 (half ? klg : khg) + (size_t)row*HIDD + gw*8);
        }
        const float* vg = Vp + ((size_t)(b*(SS/2) + kt*32))*HIDD + h*64;
        #pragma unroll
        for (int i = 0; i < 4; i++){
            int idx = tid + i*128;
            int kp = idx >> 4, gw = idx & 15;
            int dst = kp*64 + ((gw ^ ((kp&3)<<1)) << 2);
            cp16(smem_u32(sm + V0 + st*2048 + dst), vg + (size_t)kp*HIDD + gw*4);
        }
    };

    load_tile(0, 0); cp_commit();

    float acc_o[8][4];
    #pragma unroll
    for (int nt = 0; nt < 8; nt++)
        #pragma unroll
        for (int r = 0; r < 4; r++) acc_o[nt][r] = 0.f;
    float mrow0 = -1e30f, mrow1 = -1e30f;
    float lrow0 = 0.f, lrow1 = 0.f;

    const int r   = wid*16 + g;            // 0..63
    const int swr = g << 2;
    const int rA0 = r*32, rA1 = (r+8)*32;
    const float* brow0 = bias + ((size_t)(b*SS + m0 + r))*SS;
    const float* brow1 = brow0 + (size_t)8*SS;

    for (int kt = 0; kt < SS/64; kt++){
        int cur = kt & 1;
        // bias prefetch for this tile (LDG, covered by QK mma latency)
        float2 bpre0[8], bpre1[8];
        #pragma unroll
        for (int nt = 0; nt < 8; nt++){
            bpre0[nt] = *(const float2*)&brow0[kt*64 + nt*8 + tig*2];
            bpre1[nt] = *(const float2*)&brow1[kt*64 + nt*8 + tig*2];
        }
        if (kt + 1 < SS/64){ load_tile(kt+1, cur^1); cp_commit(); cp_wait<1>(); }
        else cp_wait<0>();
        __syncthreads();

        const float* Kph = sm + KH0 + cur*2048;
        const float* Kpl = sm + KL0 + cur*2048;
        const float* Vs  = sm + V0  + cur*2048;

        float acc_s[8][4];
        #pragma unroll
        for (int nt = 0; nt < 8; nt++)
            #pragma unroll
            for (int q = 0; q < 4; q++) acc_s[nt][q] = 0.f;

        #pragma unroll
        for (int ks = 0; ks < 4; ks++){
            int w0 = ks*8 + tig;
            uint32_t qhf[4], qlf[4];
            qhf[0] = *(const uint32_t*)&sm[QHo + rA0 + (w0 ^ swr)];
            qhf[1] = *(const uint32_t*)&sm[QHo + rA1 + (w0 ^ swr)];
            qhf[2] = *(const uint32_t*)&sm[QHo + rA0 + ((w0+4) ^ swr)];
            qhf[3] = *(const uint32_t*)&sm[QHo + rA1 + ((w0+4) ^ swr)];
            if (ks < 2){
                qlf[0] = *(const uint32_t*)&sm[QLo + rA0 + (w0 ^ swr)];
                qlf[1] = *(const uint32_t*)&sm[QLo + rA1 + (w0 ^ swr)];
                qlf[2] = *(const uint32_t*)&sm[QLo + rA0 + ((w0+4) ^ swr)];
                qlf[3] = *(const uint32_t*)&sm[QLo + rA1 + ((w0+4) ^ swr)];
            }
            #pragma unroll
            for (int nt = 0; nt < 8; nt++){
                int n = nt*8 + g;
                int ro = n*32, swn = (n&7) << 2;
                uint32_t khf[2];
                khf[0] = *(const uint32_t*)&Kph[ro + (w0 ^ swn)];
                khf[1] = *(const uint32_t*)&Kph[ro + ((w0+4) ^ swn)];
                mma16h(acc_s[nt], qhf, khf);
                if (ks < 2){
                    uint32_t klf[2];
                    klf[0] = *(const uint32_t*)&Kpl[ro + (w0 ^ swn)];
                    klf[1] = *(const uint32_t*)&Kpl[ro + ((w0+4) ^ swn)];
                    mma16h(acc_s[nt], qhf, klf);
                    mma16h(acc_s[nt], qlf, khf);
                }
            }
        }

        // ---- streaming softmax update ----
        float mx0 = acc_s[0][0], mx1 = acc_s[0][2];
        #pragma unroll
        for (int nt = 0; nt < 8; nt++){
            mx0 = fmaxf(mx0, fmaxf(acc_s[nt][0], acc_s[nt][1]));
            mx1 = fmaxf(mx1, fmaxf(acc_s[nt][2], acc_s[nt][3]));
        }
        #pragma unroll
        for (int o = 1; o < 4; o <<= 1){
            mx0 = fmaxf(mx0, __shfl_xor_sync(0xffffffffu, mx0, o));
            mx1 = fmaxf(mx1, __shfl_xor_sync(0xffffffffu, mx1, o));
        }
        float mn0 = fmaxf(mrow0, mx0);
        float mn1 = fmaxf(mrow1, mx1);
        float cr0 = __expf(mrow0 - mn0);
        float cr1 = __expf(mrow1 - mn1);
        mrow0 = mn0; mrow1 = mn1;
        lrow0 *= cr0; lrow1 *= cr1;
        #pragma unroll
        for (int nt = 0; nt < 8; nt++){
            acc_o[nt][0] *= cr0; acc_o[nt][1] *= cr0;
            acc_o[nt][2] *= cr1; acc_o[nt][3] *= cr1;
        }

        // exp, accumulate l (bias excluded), stage single-fp16 P*bias
        #pragma unroll
        for (int nt = 0; nt < 8; nt++){
            float p0 = __expf(acc_s[nt][0] - mn0);
            float p1 = __expf(acc_s[nt][1] - mn0);
            float p2 = __expf(acc_s[nt][2] - mn1);
            float p3 = __expf(acc_s[nt][3] - mn1);
            lrow0 += p0 + p1;
            lrow1 += p2 + p3;
            float v0 = p0*bpre0[nt].x, v1 = p1*bpre0[nt].y;
            float v2 = p2*bpre1[nt].x, v3 = p3*bpre1[nt].y;
            int wc = (nt*4 + tig) ^ swr;
            *(uint32_t*)&sm[PHo + rA0 + wc] =
                pack2h(__float2half_rn(v0), __float2half_rn(v1));
            *(uint32_t*)&sm[PHo + rA1 + wc] =
                pack2h(__float2half_rn(v2), __float2half_rn(v3));
        }
        __syncwarp();

        // ---- O += P . V  (single x single) ----
        #pragma unroll
        for (int ks = 0; ks < 4; ks++){
            int w0 = ks*8 + tig;
            uint32_t phf[4];
            phf[0] = *(const uint32_t*)&sm[PHo + rA0 + (w0 ^ swr)];
            phf[1] = *(const uint32_t*)&sm[PHo + rA1 + (w0 ^ swr)];
            phf[2] = *(const uint32_t*)&sm[PHo + rA0 + ((w0+4) ^ swr)];
            phf[3] = *(const uint32_t*)&sm[PHo + rA1 + ((w0+4) ^ swr)];
            int base0 = w0*64, base1 = (w0+4)*64;
            int swv = tig << 3;
            #pragma unroll
            for (int nt = 0; nt < 8; nt++){
                int d = nt*8 + g;
                uint32_t vf[2];
                vf[0] = *(const uint32_t*)&Vs[base0 + (d ^ swv)];
                vf[1] = *(const uint32_t*)&Vs[base1 + (d ^ swv)];
                mma16h(acc_o[nt], phf, vf);
            }
        }
        __syncthreads();
    }

    #pragma unroll
    for (int o = 1; o < 4; o <<= 1){
        lrow0 += __shfl_xor_sync(0xffffffffu, lrow0, o);
        lrow1 += __shfl_xor_sync(0xffffffffu, lrow1, o);
    }
    float inv0 = 1.f / lrow0, inv1 = 1.f / lrow1;
    int grow = m0 + r;
    #pragma unroll
    for (int nt = 0; nt < 8; nt++){
        int col = h*64 + nt*8 + tig*2;
        float o0 = acc_o[nt][0]*inv0, o1 = acc_o[nt][1]*inv0;
        float o2 = acc_o[nt][2]*inv1, o3 = acc_o[nt][3]*inv1;
        __nv_bfloat16 h0,l0,h1,l1,h2,l2,h3,l3;
        split1(o0,h0,l0); split1(o1,h1,l1);
        split1(o2,h2,l2); split1(o3,h3,l3);
        size_t off0 = ((size_t)(b*SS + grow    ))*HIDD + col;
        size_t off1 = ((size_t)(b*SS + grow + 8))*HIDD + col;
        *(uint32_t*)&Ch[off0] = pack2(h0,h1);
        *(uint32_t*)&Cl[off0] = pack2(l0,l1);
        *(uint32_t*)&Ch[off1] = pack2(h2,h3);
        *(uint32_t*)&Cl[off1] = pack2(l2,l3);
    }
}

// ---------------------------------------------------------------------------
extern "C" void kernel_launch(void* const* d_in, const int* in_sizes, int n_in,
                              void* d_out, int out_size)
{
    const float* x    = (const float*)d_in[0];
    const float* sinu = (const float*)d_in[1];
    const float* bias = (const float*)d_in[2];
    const float* Wq   = (const float*)d_in[3];
    const float* bq   = (const float*)d_in[4];
    const float* Wk   = (const float*)d_in[5];
    const float* bk   = (const float*)d_in[6];
    const float* Wv   = (const float*)d_in[7];
    const float* bv   = (const float*)d_in[8];
    const float* Wo   = (const float*)d_in[9];
    float* out = (float*)d_out;

    float *Vp, *Wh, *Wl, *Fq, *Fk;
    __half *Qh, *Ql, *Kh, *Kl;
    __nv_bfloat16 *Ch, *Cl, *Xh, *Xl;
    cudaGetSymbolAddress((void**)&Qh, g_Qh);  cudaGetSymbolAddress((void**)&Ql, g_Ql);
    cudaGetSymbolAddress((void**)&Kh, g_Kh);  cudaGetSymbolAddress((void**)&Kl, g_Kl);
    cudaGetSymbolAddress((void**)&Vp, g_Vp);
    cudaGetSymbolAddress((void**)&Ch, g_Ch);  cudaGetSymbolAddress((void**)&Cl, g_Cl);
    cudaGetSymbolAddress((void**)&Xh, g_Xh);  cudaGetSymbolAddress((void**)&Xl, g_Xl);
    cudaGetSymbolAddress((void**)&Wh, g_Wh);  cudaGetSymbolAddress((void**)&Wl, g_Wl);
    cudaGetSymbolAddress((void**)&Fq, g_Fq);  cudaGetSymbolAddress((void**)&Fk, g_Fk);
    const int WSTRIDE = (HIDD/2)*HIDD;

    cudaFuncSetAttribute(gemm_sb<0>, cudaFuncAttributeMaxDynamicSharedMemorySize, 73728);
    cudaFuncSetAttribute(gemm_sb<1>, cudaFuncAttributeMaxDynamicSharedMemorySize, 73728);
    cudaFuncSetAttribute(gemm_sb<2>, cudaFuncAttributeMaxDynamicSharedMemorySize, 73728);
    cudaFuncSetAttribute(flash_attn, cudaFuncAttributeMaxDynamicSharedMemorySize, 73728);
    cudaFuncSetAttribute(flash_attn, cudaFuncAttributePreferredSharedMemoryCarveout, 100);

    // prep
    split_x_k<<<(NELEM/2 + 255)/256, 256>>>((const float2*)x,
        (__nv_bfloat162*)Xh, (__nv_bfloat162*)Xl, NELEM/2);
    split_w_k<<<(WSTRIDE + 255)/256, 256>>>(Wq, (uint32_t*)(Wh + 0*WSTRIDE), (uint32_t*)(Wl + 0*WSTRIDE));
    split_w_k<<<(WSTRIDE + 255)/256, 256>>>(Wk, (uint32_t*)(Wh + 1*WSTRIDE), (uint32_t*)(Wl + 1*WSTRIDE));
    split_w_k<<<(WSTRIDE + 255)/256, 256>>>(Wv, (uint32_t*)(Wh + 2*WSTRIDE), (uint32_t*)(Wl + 2*WSTRIDE));
    split_w_k<<<(WSTRIDE + 255)/256, 256>>>(Wo, (uint32_t*)(Wh + 3*WSTRIDE), (uint32_t*)(Wl + 3*WSTRIDE));
    factors_k<<<(64*MTOT + 255)/256, 256>>>(sinu, Fq, Fk);

    // projections with fused epilogues
    dim3 gg(HIDD/128, MTOT/128);   // (8, 32)
    gemm_sb<0><<<gg, 256, 73728>>>(Xh, Xl, Wh + 0*WSTRIDE, Wl + 0*WSTRIDE, bq, Fq, Qh, Ql);
    gemm_sb<0><<<gg, 256, 73728>>>(Xh, Xl, Wh + 1*WSTRIDE, Wl + 1*WSTRIDE, bk, Fk, Kh, Kl);
    gemm_sb<1><<<gg, 256, 73728>>>(Xh, Xl, Wh + 2*WSTRIDE, Wl + 2*WSTRIDE, bv, nullptr, Vp, nullptr);

    // fused attention: 64-row q tiles, h fastest for bias L2 reuse
    flash_attn<<<dim3(NH, SS/64, BB), 128, 73728>>>(Qh, Ql, Kh, Kl, Vp, bias, Ch, Cl);

    // output projection
    gemm_sb<2><<<gg, 256, 73728>>>(Ch, Cl, Wh + 3*WSTRIDE, Wl + 3*WSTRIDE, nullptr, nullptr, out, nullptr);
}